// round 1
// baseline (speedup 1.0000x reference)
#include <cuda_runtime.h>
#include <cuda_bf16.h>
#include <math.h>

// ---------------------------------------------------------------------------
// ScoreMagnitudeMetric:
//   n2p[p]  = ||pos_p @ W||^2
//   alpha   = (1.0 - 0.001) / (max(n2p^2) - min(n2p^2))
//   beta    = 0.001 - alpha * min(n2p^2)
//   n2x[b]  = ||x_b @ W||^2
//   out[b]  = (alpha * n2x[b]^2 + beta) * sum(x_dot[b]^2)
// ---------------------------------------------------------------------------

#define MAXB 32768
#define MAXP 2048
#define NSPLIT_POS 16

__device__ float g_n2x[MAXB];                   // ||x_b W||^2
__device__ float g_parts[NSPLIT_POS * MAXP];    // pos partial norms per N-split
__device__ float g_ab[2];                       // alpha, beta

// ---------------------------------------------------------------------------
// Tiled GEMM-norm: for each row m of A (M x D), computes
//   sum over j in [ntBegin*64, ntEnd*64) of (A[m,:] . W[:,j])^2
// Block tile 64 rows; sweeps ntPerBlock N-tiles of 64 columns; K-tiles of 32.
// 256 threads, 4x4 register micro-tiles. Deterministic (shuffle reductions).
// out[blockIdx.y * outStrideY + m] = partial row norm^2  (direct store, no atomics)
// ---------------------------------------------------------------------------
__global__ __launch_bounds__(256, 4)
void gemm_norm_kernel(const float* __restrict__ A,
                      const float* __restrict__ W,
                      int D, int ntPerBlock,
                      float* __restrict__ out, int outStrideY)
{
    __shared__ float As[32][65];   // [k][m], padded
    __shared__ float Bs[32][65];   // [k][j], padded

    const int t  = threadIdx.x;
    const int ty = t >> 4;         // 0..15  (row group)
    const int tx = t & 15;         // 0..15  (col group)
    const int m0 = blockIdx.x * 64;
    const int ntBegin = blockIdx.y * ntPerBlock;

    float rn[4] = {0.f, 0.f, 0.f, 0.f};

    for (int nt = ntBegin; nt < ntBegin + ntPerBlock; ++nt) {
        const int j0 = nt * 64;
        float acc[4][4];
        #pragma unroll
        for (int i = 0; i < 4; ++i)
            #pragma unroll
            for (int j = 0; j < 4; ++j) acc[i][j] = 0.f;

        for (int kb = 0; kb < D; kb += 32) {
            // Load A tile: 64 rows x 32 k  (coalesced; store transposed)
            #pragma unroll
            for (int i = 0; i < 8; ++i) {
                int idx = t + 256 * i;
                int k = idx & 31, m = idx >> 5;
                As[k][m] = A[(size_t)(m0 + m) * D + kb + k];
            }
            // Load W tile: 32 k x 64 j  (coalesced)
            #pragma unroll
            for (int i = 0; i < 8; ++i) {
                int idx = t + 256 * i;
                int j = idx & 63, k = idx >> 6;
                Bs[k][j] = W[(size_t)(kb + k) * D + j0 + j];
            }
            __syncthreads();

            #pragma unroll
            for (int k = 0; k < 32; ++k) {
                float a0 = As[k][ty * 4 + 0];
                float a1 = As[k][ty * 4 + 1];
                float a2 = As[k][ty * 4 + 2];
                float a3 = As[k][ty * 4 + 3];
                float b0 = Bs[k][tx * 4 + 0];
                float b1 = Bs[k][tx * 4 + 1];
                float b2 = Bs[k][tx * 4 + 2];
                float b3 = Bs[k][tx * 4 + 3];
                acc[0][0] += a0 * b0; acc[0][1] += a0 * b1; acc[0][2] += a0 * b2; acc[0][3] += a0 * b3;
                acc[1][0] += a1 * b0; acc[1][1] += a1 * b1; acc[1][2] += a1 * b2; acc[1][3] += a1 * b3;
                acc[2][0] += a2 * b0; acc[2][1] += a2 * b1; acc[2][2] += a2 * b2; acc[2][3] += a2 * b3;
                acc[3][0] += a3 * b0; acc[3][1] += a3 * b1; acc[3][2] += a3 * b2; acc[3][3] += a3 * b3;
            }
            __syncthreads();
        }

        // Square-accumulate this N-tile's scores into the per-row norm partials
        #pragma unroll
        for (int i = 0; i < 4; ++i) {
            rn[i] += acc[i][0] * acc[i][0] + acc[i][1] * acc[i][1]
                   + acc[i][2] * acc[i][2] + acc[i][3] * acc[i][3];
        }
    }

    // Reduce across the 16 tx threads sharing each row group.
    // t = ty*16 + tx  =>  the 16 partners are contiguous lanes in one warp.
    #pragma unroll
    for (int i = 0; i < 4; ++i) {
        #pragma unroll
        for (int off = 8; off > 0; off >>= 1)
            rn[i] += __shfl_down_sync(0xFFFFFFFFu, rn[i], off, 16);
    }
    if (tx == 0) {
        float* dst = out + (size_t)blockIdx.y * outStrideY + m0;
        #pragma unroll
        for (int i = 0; i < 4; ++i)
            dst[ty * 4 + i] = rn[i];
    }
}

// ---------------------------------------------------------------------------
// Calibration: reduce per-row partials -> norm^4 -> max/min -> alpha, beta.
// Single block, deterministic tree reduction.
// ---------------------------------------------------------------------------
__global__ void calib_kernel(const float* __restrict__ parts, int P, int nparts,
                             float* __restrict__ ab)
{
    __shared__ float smx[256], smn[256];
    const int tid = threadIdx.x;
    float mx = -1e30f, mn = 1e30f;
    for (int r = tid; r < P; r += 256) {
        float tot = 0.f;
        for (int y = 0; y < nparts; ++y)
            tot += parts[(size_t)y * P + r];
        float n4 = tot * tot;           // (norm^2)^2 = norm^4
        mx = fmaxf(mx, n4);
        mn = fminf(mn, n4);
    }
    smx[tid] = mx; smn[tid] = mn;
    __syncthreads();
    for (int s = 128; s > 0; s >>= 1) {
        if (tid < s) {
            smx[tid] = fmaxf(smx[tid], smx[tid + s]);
            smn[tid] = fminf(smn[tid], smn[tid + s]);
        }
        __syncthreads();
    }
    if (tid == 0) {
        float alpha = (1.0f - 0.001f) / (smx[0] - smn[0]);
        ab[0] = alpha;
        ab[1] = 0.001f - alpha * smn[0];
    }
}

// ---------------------------------------------------------------------------
// Finalize: one warp per row. d2 = ||x_dot_b||^2 via vectorized loads,
// out[b] = (alpha * n2^2 + beta) * d2.
// ---------------------------------------------------------------------------
__global__ __launch_bounds__(256)
void finalize_kernel(const float* __restrict__ x_dot,
                     const float* __restrict__ n2,
                     const float* __restrict__ ab,
                     float* __restrict__ out, int B, int D)
{
    const int warp = (blockIdx.x * blockDim.x + threadIdx.x) >> 5;
    const int lane = threadIdx.x & 31;
    if (warp >= B) return;

    const int D4 = D >> 2;  // float4 elements per row
    const float4* xd = reinterpret_cast<const float4*>(x_dot) + (size_t)warp * D4;
    float s = 0.f;
    for (int i = lane; i < D4; i += 32) {
        float4 v = xd[i];
        s += v.x * v.x + v.y * v.y + v.z * v.z + v.w * v.w;
    }
    #pragma unroll
    for (int off = 16; off > 0; off >>= 1)
        s += __shfl_down_sync(0xFFFFFFFFu, s, off);

    if (lane == 0) {
        float a = ab[0], b = ab[1];
        float t = n2[warp];
        out[warp] = (a * t * t + b) * s;
    }
}

// ---------------------------------------------------------------------------
// kernel_launch
// Inputs (metadata order): x (B*D f32), x_dot (B*D f32),
//                          pos_sample (P*D f32), W (D*D f32)
// Output: (B,) f32
// ---------------------------------------------------------------------------
extern "C" void kernel_launch(void* const* d_in, const int* in_sizes, int n_in,
                              void* d_out, int out_size)
{
    const float* x     = (const float*)d_in[0];
    const float* x_dot = (const float*)d_in[1];
    const float* pos   = (const float*)d_in[2];
    const float* W     = (const float*)d_in[3];
    float* out = (float*)d_out;

    const int D = (int)(sqrt((double)in_sizes[3]) + 0.5);
    const int B = in_sizes[0] / D;
    const int P = in_sizes[2] / D;

    float *n2x = nullptr, *parts = nullptr, *ab = nullptr;
    cudaGetSymbolAddress((void**)&n2x,   g_n2x);
    cudaGetSymbolAddress((void**)&parts, g_parts);
    cudaGetSymbolAddress((void**)&ab,    g_ab);

    const int nTiles = D / 64;   // 16 for D=1024

    // x GEMM-norm: one block per 64 rows, sweeps all N-tiles -> direct store
    gemm_norm_kernel<<<dim3(B / 64, 1), 256>>>(x, W, D, nTiles, n2x, 0);

    // pos GEMM-norm: split N across gridDim.y for parallelism -> partial buffer
    gemm_norm_kernel<<<dim3(P / 64, NSPLIT_POS), 256>>>(
        pos, W, D, nTiles / NSPLIT_POS, parts, P);

    // alpha/beta
    calib_kernel<<<1, 256>>>(parts, P, NSPLIT_POS, ab);

    // fused rowsum(x_dot^2) + scale
    const int rows_per_block = 256 / 32;
    finalize_kernel<<<(B + rows_per_block - 1) / rows_per_block, 256>>>(
        x_dot, n2x, ab, out, B, D);
}

// round 3
// speedup vs baseline: 3.8065x; 3.8065x over previous
#include <cuda_runtime.h>
#include <cuda_bf16.h>
#include <math.h>
#include <stdint.h>

// ===========================================================================
// ScoreMagnitudeMetric via warp-level mma.sync bf16 split GEMM (sm_100-safe):
//   scores = x @ W computed as xh@Wth + xh@Wtl + xl@Wth (bf16 hi/lo split,
//   fp32 accumulation), Wt = W^T so D[m,n] = sum_k A[m,k] * Wt[n,k].
//   n2[b] = ||scores_b||^2 ; out[b] = (alpha*n2^2 + beta) * ||x_dot_b||^2
// ===========================================================================

#define MAXB 32768
#define MAXP 2048
#define MAXD 1024

#define BM 128
#define BN 128
#define BK 32
#define NSLICE_MAX (MAXD / BN)   // 8

// scratch (device globals; no allocation allowed)
__device__ __nv_bfloat16 g_xh[(size_t)MAXB * MAXD];
__device__ __nv_bfloat16 g_xl[(size_t)MAXB * MAXD];
__device__ __nv_bfloat16 g_ph[(size_t)MAXP * MAXD];
__device__ __nv_bfloat16 g_pl[(size_t)MAXP * MAXD];
__device__ __nv_bfloat16 g_wh[(size_t)MAXD * MAXD];   // W^T hi
__device__ __nv_bfloat16 g_wl[(size_t)MAXD * MAXD];   // W^T lo
__device__ float g_xparts[NSLICE_MAX * MAXB];
__device__ float g_pparts[NSLICE_MAX * MAXP];
__device__ float g_ab[2];

// ---------------------------------------------------------------------------
// helpers
// ---------------------------------------------------------------------------
__device__ __forceinline__ uint32_t smem_to_u32(const void* p) {
    uint32_t a;
    asm("{ .reg .u64 t; cvta.to.shared.u64 t, %1; cvt.u32.u64 %0, t; }"
        : "=r"(a) : "l"(p));
    return a;
}

#define CP_ASYNC16(sm, g) \
    asm volatile("cp.async.cg.shared.global [%0], [%1], 16;" :: "r"(sm), "l"(g) : "memory")
#define CP_COMMIT()  asm volatile("cp.async.commit_group;" ::: "memory")
#define CP_WAIT1()   asm volatile("cp.async.wait_group 1;" ::: "memory")
#define CP_WAIT0()   asm volatile("cp.async.wait_group 0;" ::: "memory")

__device__ __forceinline__ void ldsm_x4(uint32_t* r, uint32_t addr) {
    asm volatile("ldmatrix.sync.aligned.m8n8.x4.shared.b16 {%0,%1,%2,%3}, [%4];"
                 : "=r"(r[0]), "=r"(r[1]), "=r"(r[2]), "=r"(r[3]) : "r"(addr));
}

__device__ __forceinline__ void mma16816(float* c, const uint32_t* a,
                                         uint32_t b0, uint32_t b1) {
    asm volatile(
        "mma.sync.aligned.m16n8k16.row.col.f32.bf16.bf16.f32 "
        "{%0,%1,%2,%3}, {%4,%5,%6,%7}, {%8,%9}, {%0,%1,%2,%3};"
        : "+f"(c[0]), "+f"(c[1]), "+f"(c[2]), "+f"(c[3])
        : "r"(a[0]), "r"(a[1]), "r"(a[2]), "r"(a[3]), "r"(b0), "r"(b1));
}

// ---------------------------------------------------------------------------
// Prep: fp32 -> (hi, lo) bf16 split, element-wise (vectorized by 4)
// ---------------------------------------------------------------------------
__global__ void split_kernel(const float* __restrict__ src,
                             __nv_bfloat16* __restrict__ hi,
                             __nv_bfloat16* __restrict__ lo, int n4)
{
    int i = blockIdx.x * blockDim.x + threadIdx.x;
    if (i >= n4) return;
    float4 v = reinterpret_cast<const float4*>(src)[i];
    __nv_bfloat16 h0 = __float2bfloat16_rn(v.x);
    __nv_bfloat16 h1 = __float2bfloat16_rn(v.y);
    __nv_bfloat16 h2 = __float2bfloat16_rn(v.z);
    __nv_bfloat16 h3 = __float2bfloat16_rn(v.w);
    __nv_bfloat16 l0 = __float2bfloat16_rn(v.x - __bfloat162float(h0));
    __nv_bfloat16 l1 = __float2bfloat16_rn(v.y - __bfloat162float(h1));
    __nv_bfloat16 l2 = __float2bfloat16_rn(v.z - __bfloat162float(h2));
    __nv_bfloat16 l3 = __float2bfloat16_rn(v.w - __bfloat162float(h3));
    __nv_bfloat162* hp = reinterpret_cast<__nv_bfloat162*>(hi) + 2 * i;
    __nv_bfloat162* lp = reinterpret_cast<__nv_bfloat162*>(lo) + 2 * i;
    hp[0] = __nv_bfloat162(h0, h1);
    hp[1] = __nv_bfloat162(h2, h3);
    lp[0] = __nv_bfloat162(l0, l1);
    lp[1] = __nv_bfloat162(l2, l3);
}

// W [k][j] -> Wt [j][k] hi/lo split (32x32 smem transpose tiles)
__global__ void wsplit_kernel(const float* __restrict__ W,
                              __nv_bfloat16* __restrict__ wth,
                              __nv_bfloat16* __restrict__ wtl, int D)
{
    __shared__ float t[32][33];
    const int j0 = blockIdx.x * 32, k0 = blockIdx.y * 32;
    const int tx = threadIdx.x, ty = threadIdx.y;  // (32, 8)
    #pragma unroll
    for (int r = 0; r < 4; ++r)
        t[ty + 8 * r][tx] = W[(size_t)(k0 + ty + 8 * r) * D + j0 + tx];
    __syncthreads();
    #pragma unroll
    for (int r = 0; r < 4; ++r) {
        float v = t[tx][ty + 8 * r];
        __nv_bfloat16 h = __float2bfloat16_rn(v);
        __nv_bfloat16 l = __float2bfloat16_rn(v - __bfloat162float(h));
        size_t o = (size_t)(j0 + ty + 8 * r) * D + k0 + tx;
        wth[o] = h;
        wtl[o] = l;
    }
}

// ---------------------------------------------------------------------------
// mma.sync GEMM-norm.
// Block: 128 rows x 128 cols, K swept in 32-chunks, cp.async double-buffer.
// Smem tile layout: K-major rows of 32 halves, row stride 80 B (5 x 16B units
// -> (5r+c) mod 8 covers all bank groups: conflict-free ldmatrix, no swizzle).
// parts[blockIdx.y * rowStride + m] = sum of squares over this 128-col slice.
// ---------------------------------------------------------------------------
#define TILE_B   10240              // 128 rows * 80 B
#define AH_OFF   0
#define AL_OFF   (TILE_B)
#define BH_OFF   (2 * TILE_B)
#define BL_OFF   (3 * TILE_B)
#define STAGE_B  (4 * TILE_B)       // 40960
#define SMEM_TOTAL (2 * STAGE_B)    // 81920

__global__ __launch_bounds__(256, 1)
void mma_gemm_norm(const __nv_bfloat16* __restrict__ Ah,
                   const __nv_bfloat16* __restrict__ Al,
                   const __nv_bfloat16* __restrict__ Bh,
                   const __nv_bfloat16* __restrict__ Bl,
                   int D, float* __restrict__ parts, int rowStride)
{
    extern __shared__ __align__(128) char smem[];
    const uint32_t sm0 = smem_to_u32(smem);

    const int tid  = threadIdx.x;
    const int wid  = tid >> 5;
    const int lane = tid & 31;
    const int wm   = wid >> 2;          // 0..1  -> rows wm*64
    const int wn   = wid & 3;           // 0..3  -> cols wn*32
    const int m0   = blockIdx.x * BM;
    const int n0   = blockIdx.y * BN;
    const int KC   = D / BK;

    const __nv_bfloat16* gAh = Ah + (size_t)m0 * D;
    const __nv_bfloat16* gAl = Al + (size_t)m0 * D;
    const __nv_bfloat16* gBh = Bh + (size_t)n0 * D;
    const __nv_bfloat16* gBl = Bl + (size_t)n0 * D;

    float acc[4][4][4];
    #pragma unroll
    for (int i = 0; i < 4; ++i)
        #pragma unroll
        for (int j = 0; j < 4; ++j)
            #pragma unroll
            for (int c = 0; c < 4; ++c) acc[i][j][c] = 0.f;

    auto load_chunk = [&](int kc, int s) {
        const uint32_t sb = sm0 + (uint32_t)s * STAGE_B;
        const int kb = kc * BK;          // halves
        #pragma unroll
        for (int i = 0; i < 2; ++i) {
            int idx = tid + 256 * i;     // 0..511
            int r = idx >> 2, c = idx & 3;
            uint32_t so = (uint32_t)(r * 80 + c * 16);
            size_t go = (size_t)r * D + kb + c * 8;
            CP_ASYNC16(sb + AH_OFF + so, gAh + go);
            CP_ASYNC16(sb + AL_OFF + so, gAl + go);
            CP_ASYNC16(sb + BH_OFF + so, gBh + go);
            CP_ASYNC16(sb + BL_OFF + so, gBl + go);
        }
    };

    // ldmatrix per-lane address pieces
    const int a_row = (lane & 15);                         // + mrow + mt*16
    const int a_ku  = (lane >> 4);                         // + kub
    const int b_row = ((lane >> 4) << 3) + (lane & 7);     // + nrow + ng*16
    const int b_ku  = ((lane >> 3) & 1);                   // + kub
    const int mrow  = wm * 64;
    const int nrow  = wn * 32;

    load_chunk(0, 0);
    CP_COMMIT();

    for (int kc = 0; kc < KC; ++kc) {
        const int s = kc & 1;
        if (kc + 1 < KC) {
            load_chunk(kc + 1, s ^ 1);
            CP_COMMIT();
            CP_WAIT1();
        } else {
            CP_WAIT0();
        }
        __syncthreads();

        const uint32_t sb = sm0 + (uint32_t)s * STAGE_B;
        #pragma unroll
        for (int ks = 0; ks < 2; ++ks) {        // two k16 steps per chunk
            const int kub = ks * 2;
            uint32_t ah[4][4], al[4][4], bh[2][4], bl[2][4];
            #pragma unroll
            for (int mt = 0; mt < 4; ++mt) {
                uint32_t off = (uint32_t)((mrow + mt * 16 + a_row) * 80
                                          + (kub + a_ku) * 16);
                ldsm_x4(ah[mt], sb + AH_OFF + off);
                ldsm_x4(al[mt], sb + AL_OFF + off);
            }
            #pragma unroll
            for (int ng = 0; ng < 2; ++ng) {
                uint32_t off = (uint32_t)((nrow + ng * 16 + b_row) * 80
                                          + (kub + b_ku) * 16);
                ldsm_x4(bh[ng], sb + BH_OFF + off);
                ldsm_x4(bl[ng], sb + BL_OFF + off);
            }
            #pragma unroll
            for (int mt = 0; mt < 4; ++mt) {
                #pragma unroll
                for (int nt = 0; nt < 4; ++nt) {
                    uint32_t bh0 = bh[nt >> 1][2 * (nt & 1)];
                    uint32_t bh1 = bh[nt >> 1][2 * (nt & 1) + 1];
                    uint32_t bl0 = bl[nt >> 1][2 * (nt & 1)];
                    uint32_t bl1 = bl[nt >> 1][2 * (nt & 1) + 1];
                    mma16816(acc[mt][nt], ah[mt], bh0, bh1);
                    mma16816(acc[mt][nt], ah[mt], bl0, bl1);
                    mma16816(acc[mt][nt], al[mt], bh0, bh1);
                }
            }
        }
        __syncthreads();
    }

    // ---- epilogue: row-wise sum of squares -------------------------------
    // acc c0,c1 -> row (lane>>2); c2,c3 -> row (lane>>2)+8  within each m16.
    float* rbuf = reinterpret_cast<float*>(smem);   // [128][4]
    float rs0[4], rs1[4];
    #pragma unroll
    for (int mt = 0; mt < 4; ++mt) {
        float s0 = 0.f, s1 = 0.f;
        #pragma unroll
        for (int nt = 0; nt < 4; ++nt) {
            s0 += acc[mt][nt][0] * acc[mt][nt][0] + acc[mt][nt][1] * acc[mt][nt][1];
            s1 += acc[mt][nt][2] * acc[mt][nt][2] + acc[mt][nt][3] * acc[mt][nt][3];
        }
        // reduce the 4 lanes of this row group (lanes 4q..4q+3)
        s0 += __shfl_xor_sync(0xFFFFFFFFu, s0, 1);
        s0 += __shfl_xor_sync(0xFFFFFFFFu, s0, 2);
        s1 += __shfl_xor_sync(0xFFFFFFFFu, s1, 1);
        s1 += __shfl_xor_sync(0xFFFFFFFFu, s1, 2);
        rs0[mt] = s0;
        rs1[mt] = s1;
    }
    __syncthreads();   // stage smem no longer needed
    if ((lane & 3) == 0) {
        int rq = lane >> 2;      // 0..7
        #pragma unroll
        for (int mt = 0; mt < 4; ++mt) {
            int row = mrow + mt * 16 + rq;
            rbuf[row * 4 + wn] = rs0[mt];
            rbuf[(row + 8) * 4 + wn] = rs1[mt];
        }
    }
    __syncthreads();
    if (tid < BM) {
        float tot = rbuf[tid * 4 + 0] + rbuf[tid * 4 + 1]
                  + rbuf[tid * 4 + 2] + rbuf[tid * 4 + 3];
        parts[(size_t)blockIdx.y * rowStride + m0 + tid] = tot;
    }
}

// ---------------------------------------------------------------------------
// Calibration: n2 = sum of N-slice partials; n4 = n2^2; alpha/beta from max/min
// ---------------------------------------------------------------------------
__global__ void calib_kernel(const float* __restrict__ parts, int P, int nparts,
                             float* __restrict__ ab)
{
    __shared__ float smx[256], smn[256];
    const int tid = threadIdx.x;
    float mx = -1e30f, mn = 1e30f;
    for (int r = tid; r < P; r += 256) {
        float tot = 0.f;
        for (int y = 0; y < nparts; ++y) tot += parts[(size_t)y * P + r];
        float n4 = tot * tot;
        mx = fmaxf(mx, n4);
        mn = fminf(mn, n4);
    }
    smx[tid] = mx; smn[tid] = mn;
    __syncthreads();
    for (int s = 128; s > 0; s >>= 1) {
        if (tid < s) {
            smx[tid] = fmaxf(smx[tid], smx[tid + s]);
            smn[tid] = fminf(smn[tid], smn[tid + s]);
        }
        __syncthreads();
    }
    if (tid == 0) {
        float alpha = (1.0f - 0.001f) / (smx[0] - smn[0]);
        ab[0] = alpha;
        ab[1] = 0.001f - alpha * smn[0];
    }
}

// ---------------------------------------------------------------------------
// Finalize: warp per row; n2 from N-slice partials; out = (a*n2^2+b)*||xd||^2
// ---------------------------------------------------------------------------
__global__ __launch_bounds__(256)
void finalize_kernel(const float* __restrict__ x_dot,
                     const float* __restrict__ parts, int nparts,
                     const float* __restrict__ ab,
                     float* __restrict__ out, int B, int D)
{
    const int warp = (blockIdx.x * blockDim.x + threadIdx.x) >> 5;
    const int lane = threadIdx.x & 31;
    if (warp >= B) return;

    const int D4 = D >> 2;
    const float4* xd = reinterpret_cast<const float4*>(x_dot) + (size_t)warp * D4;
    float s = 0.f;
    for (int i = lane; i < D4; i += 32) {
        float4 v = xd[i];
        s += v.x * v.x + v.y * v.y + v.z * v.z + v.w * v.w;
    }
    #pragma unroll
    for (int off = 16; off > 0; off >>= 1)
        s += __shfl_down_sync(0xFFFFFFFFu, s, off);

    if (lane == 0) {
        float n2 = 0.f;
        for (int y = 0; y < nparts; ++y) n2 += parts[(size_t)y * B + warp];
        float a = ab[0], b = ab[1];
        out[warp] = (a * n2 * n2 + b) * s;
    }
}

// ---------------------------------------------------------------------------
// kernel_launch
// ---------------------------------------------------------------------------
extern "C" void kernel_launch(void* const* d_in, const int* in_sizes, int n_in,
                              void* d_out, int out_size)
{
    const float* x     = (const float*)d_in[0];
    const float* x_dot = (const float*)d_in[1];
    const float* pos   = (const float*)d_in[2];
    const float* W     = (const float*)d_in[3];
    float* out = (float*)d_out;

    const int D = (int)(sqrt((double)in_sizes[3]) + 0.5);
    const int B = in_sizes[0] / D;
    const int P = in_sizes[2] / D;
    const int NS = D / BN;   // 8 N-slices

    __nv_bfloat16 *xh, *xl, *ph, *pl, *wh, *wl;
    float *xparts, *pparts, *ab;
    cudaGetSymbolAddress((void**)&xh, g_xh);
    cudaGetSymbolAddress((void**)&xl, g_xl);
    cudaGetSymbolAddress((void**)&ph, g_ph);
    cudaGetSymbolAddress((void**)&pl, g_pl);
    cudaGetSymbolAddress((void**)&wh, g_wh);
    cudaGetSymbolAddress((void**)&wl, g_wl);
    cudaGetSymbolAddress((void**)&xparts, g_xparts);
    cudaGetSymbolAddress((void**)&pparts, g_pparts);
    cudaGetSymbolAddress((void**)&ab, g_ab);

    cudaFuncSetAttribute(mma_gemm_norm,
                         cudaFuncAttributeMaxDynamicSharedMemorySize, SMEM_TOTAL);

    // prep: hi/lo splits
    {
        int n4 = (B * D) / 4;
        split_kernel<<<(n4 + 255) / 256, 256>>>(x, xh, xl, n4);
        int p4 = (P * D) / 4;
        split_kernel<<<(p4 + 255) / 256, 256>>>(pos, ph, pl, p4);
        wsplit_kernel<<<dim3(D / 32, D / 32), dim3(32, 8)>>>(W, wh, wl, D);
    }

    // GEMM-norms (tensor cores via mma.sync)
    mma_gemm_norm<<<dim3(B / BM, NS), 256, SMEM_TOTAL>>>(xh, xl, wh, wl, D, xparts, B);
    mma_gemm_norm<<<dim3(P / BM, NS), 256, SMEM_TOTAL>>>(ph, pl, wh, wl, D, pparts, P);

    // alpha/beta
    calib_kernel<<<1, 256>>>(pparts, P, NS, ab);

    // fused rowsum(x_dot^2) + scale
    const int rows_per_block = 256 / 32;
    finalize_kernel<<<(B + rows_per_block - 1) / rows_per_block, 256>>>(
        x_dot, xparts, NS, ab, out, B, D);
}

// round 4
// speedup vs baseline: 5.9875x; 1.5730x over previous
#include <cuda_runtime.h>
#include <cuda_fp16.h>
#include <math.h>
#include <stdint.h>

// ===========================================================================
// ScoreMagnitudeMetric via warp-level mma.sync fp16 2-term GEMM (sm_100-safe):
//   x = xh + xl (fp16 hi/lo split, residual ~2^-22)
//   scores = x @ W  ~=  xh@Wth + xl@Wth   with Wth = fp16(W^T)
//   (dropped term x@(W-fp16(W)) -> per-element rel err ~2.8e-4, averages to
//    ~1.5e-4 global through the norm^2 / norm^4 / alpha chain — validated model)
//   n2[b] = ||scores_b||^2 ; out[b] = (alpha*n2^2 + beta) * ||x_dot_b||^2
// ===========================================================================

#define MAXB 32768
#define MAXP 2048
#define MAXD 1024

#define BM 128
#define BN 128
#define BK 32
#define NSLICE_MAX (MAXD / BN)   // 8

// scratch (device globals; no allocation allowed)
__device__ __half g_xh[(size_t)MAXB * MAXD];
__device__ __half g_xl[(size_t)MAXB * MAXD];
__device__ __half g_ph[(size_t)MAXP * MAXD];
__device__ __half g_pl[(size_t)MAXP * MAXD];
__device__ __half g_wh[(size_t)MAXD * MAXD];   // fp16(W^T)
__device__ float g_xparts[NSLICE_MAX * MAXB];
__device__ float g_pparts[NSLICE_MAX * MAXP];
__device__ float g_ab[2];

// ---------------------------------------------------------------------------
// helpers
// ---------------------------------------------------------------------------
__device__ __forceinline__ uint32_t smem_to_u32(const void* p) {
    uint32_t a;
    asm("{ .reg .u64 t; cvta.to.shared.u64 t, %1; cvt.u32.u64 %0, t; }"
        : "=r"(a) : "l"(p));
    return a;
}

#define CP_ASYNC16(sm, g) \
    asm volatile("cp.async.cg.shared.global [%0], [%1], 16;" :: "r"(sm), "l"(g) : "memory")
#define CP_COMMIT()  asm volatile("cp.async.commit_group;" ::: "memory")
#define CP_WAIT1()   asm volatile("cp.async.wait_group 1;" ::: "memory")
#define CP_WAIT0()   asm volatile("cp.async.wait_group 0;" ::: "memory")

__device__ __forceinline__ void ldsm_x4(uint32_t* r, uint32_t addr) {
    asm volatile("ldmatrix.sync.aligned.m8n8.x4.shared.b16 {%0,%1,%2,%3}, [%4];"
                 : "=r"(r[0]), "=r"(r[1]), "=r"(r[2]), "=r"(r[3]) : "r"(addr));
}

__device__ __forceinline__ void mma16816(float* c, const uint32_t* a,
                                         uint32_t b0, uint32_t b1) {
    asm volatile(
        "mma.sync.aligned.m16n8k16.row.col.f32.f16.f16.f32 "
        "{%0,%1,%2,%3}, {%4,%5,%6,%7}, {%8,%9}, {%0,%1,%2,%3};"
        : "+f"(c[0]), "+f"(c[1]), "+f"(c[2]), "+f"(c[3])
        : "r"(a[0]), "r"(a[1]), "r"(a[2]), "r"(a[3]), "r"(b0), "r"(b1));
}

// ---------------------------------------------------------------------------
// Prep: fp32 -> (hi, lo) fp16 split, element-wise (vectorized by 4)
// ---------------------------------------------------------------------------
__global__ void split_kernel(const float* __restrict__ src,
                             __half* __restrict__ hi,
                             __half* __restrict__ lo, int n4)
{
    int i = blockIdx.x * blockDim.x + threadIdx.x;
    if (i >= n4) return;
    float4 v = reinterpret_cast<const float4*>(src)[i];
    __half h0 = __float2half_rn(v.x);
    __half h1 = __float2half_rn(v.y);
    __half h2 = __float2half_rn(v.z);
    __half h3 = __float2half_rn(v.w);
    __half l0 = __float2half_rn(v.x - __half2float(h0));
    __half l1 = __float2half_rn(v.y - __half2float(h1));
    __half l2 = __float2half_rn(v.z - __half2float(h2));
    __half l3 = __float2half_rn(v.w - __half2float(h3));
    __half2* hp = reinterpret_cast<__half2*>(hi) + 2 * i;
    __half2* lp = reinterpret_cast<__half2*>(lo) + 2 * i;
    hp[0] = __half2(h0, h1);
    hp[1] = __half2(h2, h3);
    lp[0] = __half2(l0, l1);
    lp[1] = __half2(l2, l3);
}

// W [k][j] -> Wt [j][k] fp16 (32x32 smem transpose tiles)
__global__ void wsplit_kernel(const float* __restrict__ W,
                              __half* __restrict__ wth, int D)
{
    __shared__ float t[32][33];
    const int j0 = blockIdx.x * 32, k0 = blockIdx.y * 32;
    const int tx = threadIdx.x, ty = threadIdx.y;  // (32, 8)
    #pragma unroll
    for (int r = 0; r < 4; ++r)
        t[ty + 8 * r][tx] = W[(size_t)(k0 + ty + 8 * r) * D + j0 + tx];
    __syncthreads();
    #pragma unroll
    for (int r = 0; r < 4; ++r) {
        float v = t[tx][ty + 8 * r];
        wth[(size_t)(j0 + ty + 8 * r) * D + k0 + tx] = __float2half_rn(v);
    }
}

// ---------------------------------------------------------------------------
// mma.sync GEMM-norm, fp16 2-term.
// Block: 128 rows x 128 cols, K in 32-chunks, 3-stage cp.async pipeline with
// a single __syncthreads per chunk.  2 CTAs/SM (regs<=128, smem 90KB/CTA).
// Smem tile rows: 32 halves = 64 B data, 80 B stride (conflict-free ldmatrix).
// parts[blockIdx.y * rowStride + m] = sum of squares over this 128-col slice.
// ---------------------------------------------------------------------------
#define TILE_B   10240              // 128 rows * 80 B
#define AH_OFF   0
#define AL_OFF   (TILE_B)
#define BH_OFF   (2 * TILE_B)
#define STAGE_B  (3 * TILE_B)       // 30720
#define NSTAGE   3
#define SMEM_TOTAL (NSTAGE * STAGE_B)   // 92160

__global__ __launch_bounds__(256, 2)
void mma_gemm_norm(const __half* __restrict__ Ah,
                   const __half* __restrict__ Al,
                   const __half* __restrict__ Bh,
                   int D, float* __restrict__ parts, int rowStride)
{
    extern __shared__ __align__(128) char smem[];
    const uint32_t sm0 = smem_to_u32(smem);

    const int tid  = threadIdx.x;
    const int wid  = tid >> 5;
    const int lane = tid & 31;
    const int wm   = wid >> 2;          // 0..1  -> rows wm*64
    const int wn   = wid & 3;           // 0..3  -> cols wn*32
    const int m0   = blockIdx.x * BM;
    const int n0   = blockIdx.y * BN;
    const int KC   = D / BK;

    const __half* gAh = Ah + (size_t)m0 * D;
    const __half* gAl = Al + (size_t)m0 * D;
    const __half* gBh = Bh + (size_t)n0 * D;

    float acc[4][4][4];
    #pragma unroll
    for (int i = 0; i < 4; ++i)
        #pragma unroll
        for (int j = 0; j < 4; ++j)
            #pragma unroll
            for (int c = 0; c < 4; ++c) acc[i][j][c] = 0.f;

    auto load_chunk = [&](int kc, int s) {
        const uint32_t sb = sm0 + (uint32_t)s * STAGE_B;
        const int kb = kc * BK;          // halves
        #pragma unroll
        for (int i = 0; i < 2; ++i) {
            int idx = tid + 256 * i;     // 0..511
            int r = idx >> 2, c = idx & 3;
            uint32_t so = (uint32_t)(r * 80 + c * 16);
            size_t go = (size_t)r * D + kb + c * 8;
            CP_ASYNC16(sb + AH_OFF + so, gAh + go);
            CP_ASYNC16(sb + AL_OFF + so, gAl + go);
            CP_ASYNC16(sb + BH_OFF + so, gBh + go);
        }
    };

    // ldmatrix per-lane address pieces
    const int a_row = (lane & 15);                         // + mrow + mt*16
    const int a_ku  = (lane >> 4);                         // + kub
    const int b_row = ((lane >> 4) << 3) + (lane & 7);     // + nrow + ng*16
    const int b_ku  = ((lane >> 3) & 1);                   // + kub
    const int mrow  = wm * 64;
    const int nrow  = wn * 32;

    // prologue: two chunks in flight
    load_chunk(0, 0);
    CP_COMMIT();
    load_chunk(1, 1);
    CP_COMMIT();

    for (int kc = 0; kc < KC; ++kc) {
        const int s = kc % NSTAGE;
        if (kc < KC - 1) CP_WAIT1(); else CP_WAIT0();
        __syncthreads();          // data(kc) visible to all; stage (kc+2)%3 free
        if (kc + 2 < KC) {
            load_chunk(kc + 2, (kc + 2) % NSTAGE);
            CP_COMMIT();
        }

        const uint32_t sb = sm0 + (uint32_t)s * STAGE_B;
        #pragma unroll
        for (int ks = 0; ks < 2; ++ks) {        // two k16 steps per chunk
            const int kub = ks * 2;
            uint32_t ah[4][4], al[4][4], bh[2][4];
            #pragma unroll
            for (int mt = 0; mt < 4; ++mt) {
                uint32_t off = (uint32_t)((mrow + mt * 16 + a_row) * 80
                                          + (kub + a_ku) * 16);
                ldsm_x4(ah[mt], sb + AH_OFF + off);
                ldsm_x4(al[mt], sb + AL_OFF + off);
            }
            #pragma unroll
            for (int ng = 0; ng < 2; ++ng) {
                uint32_t off = (uint32_t)((nrow + ng * 16 + b_row) * 80
                                          + (kub + b_ku) * 16);
                ldsm_x4(bh[ng], sb + BH_OFF + off);
            }
            #pragma unroll
            for (int mt = 0; mt < 4; ++mt) {
                #pragma unroll
                for (int nt = 0; nt < 4; ++nt) {
                    uint32_t b0 = bh[nt >> 1][2 * (nt & 1)];
                    uint32_t b1 = bh[nt >> 1][2 * (nt & 1) + 1];
                    mma16816(acc[mt][nt], ah[mt], b0, b1);
                    mma16816(acc[mt][nt], al[mt], b0, b1);
                }
            }
        }
    }
    __syncthreads();   // all compute done before smem reuse below

    // ---- epilogue: row-wise sum of squares -------------------------------
    // acc c0,c1 -> row (lane>>2); c2,c3 -> row (lane>>2)+8 within each m16.
    float* rbuf = reinterpret_cast<float*>(smem);   // [128][4]
    float rs0[4], rs1[4];
    #pragma unroll
    for (int mt = 0; mt < 4; ++mt) {
        float s0 = 0.f, s1 = 0.f;
        #pragma unroll
        for (int nt = 0; nt < 4; ++nt) {
            s0 += acc[mt][nt][0] * acc[mt][nt][0] + acc[mt][nt][1] * acc[mt][nt][1];
            s1 += acc[mt][nt][2] * acc[mt][nt][2] + acc[mt][nt][3] * acc[mt][nt][3];
        }
        s0 += __shfl_xor_sync(0xFFFFFFFFu, s0, 1);
        s0 += __shfl_xor_sync(0xFFFFFFFFu, s0, 2);
        s1 += __shfl_xor_sync(0xFFFFFFFFu, s1, 1);
        s1 += __shfl_xor_sync(0xFFFFFFFFu, s1, 2);
        rs0[mt] = s0;
        rs1[mt] = s1;
    }
    if ((lane & 3) == 0) {
        int rq = lane >> 2;      // 0..7
        #pragma unroll
        for (int mt = 0; mt < 4; ++mt) {
            int row = mrow + mt * 16 + rq;
            rbuf[row * 4 + wn] = rs0[mt];
            rbuf[(row + 8) * 4 + wn] = rs1[mt];
        }
    }
    __syncthreads();
    if (tid < BM) {
        float tot = rbuf[tid * 4 + 0] + rbuf[tid * 4 + 1]
                  + rbuf[tid * 4 + 2] + rbuf[tid * 4 + 3];
        parts[(size_t)blockIdx.y * rowStride + m0 + tid] = tot;
    }
}

// ---------------------------------------------------------------------------
// Calibration: n2 = sum of N-slice partials; n4 = n2^2; alpha/beta from max/min
// ---------------------------------------------------------------------------
__global__ void calib_kernel(const float* __restrict__ parts, int P, int nparts,
                             float* __restrict__ ab)
{
    __shared__ float smx[256], smn[256];
    const int tid = threadIdx.x;
    float mx = -1e30f, mn = 1e30f;
    for (int r = tid; r < P; r += 256) {
        float tot = 0.f;
        for (int y = 0; y < nparts; ++y) tot += parts[(size_t)y * P + r];
        float n4 = tot * tot;
        mx = fmaxf(mx, n4);
        mn = fminf(mn, n4);
    }
    smx[tid] = mx; smn[tid] = mn;
    __syncthreads();
    for (int s = 128; s > 0; s >>= 1) {
        if (tid < s) {
            smx[tid] = fmaxf(smx[tid], smx[tid + s]);
            smn[tid] = fminf(smn[tid], smn[tid + s]);
        }
        __syncthreads();
    }
    if (tid == 0) {
        float alpha = (1.0f - 0.001f) / (smx[0] - smn[0]);
        ab[0] = alpha;
        ab[1] = 0.001f - alpha * smn[0];
    }
}

// ---------------------------------------------------------------------------
// Finalize: warp per row; n2 from N-slice partials; out = (a*n2^2+b)*||xd||^2
// ---------------------------------------------------------------------------
__global__ __launch_bounds__(256)
void finalize_kernel(const float* __restrict__ x_dot,
                     const float* __restrict__ parts, int nparts,
                     const float* __restrict__ ab,
                     float* __restrict__ out, int B, int D)
{
    const int warp = (blockIdx.x * blockDim.x + threadIdx.x) >> 5;
    const int lane = threadIdx.x & 31;
    if (warp >= B) return;

    const int D4 = D >> 2;
    const float4* xd = reinterpret_cast<const float4*>(x_dot) + (size_t)warp * D4;
    float s = 0.f;
    for (int i = lane; i < D4; i += 32) {
        float4 v = xd[i];
        s += v.x * v.x + v.y * v.y + v.z * v.z + v.w * v.w;
    }
    #pragma unroll
    for (int off = 16; off > 0; off >>= 1)
        s += __shfl_down_sync(0xFFFFFFFFu, s, off);

    if (lane == 0) {
        float n2 = 0.f;
        for (int y = 0; y < nparts; ++y) n2 += parts[(size_t)y * B + warp];
        float a = ab[0], b = ab[1];
        out[warp] = (a * n2 * n2 + b) * s;
    }
}

// ---------------------------------------------------------------------------
// kernel_launch
// ---------------------------------------------------------------------------
extern "C" void kernel_launch(void* const* d_in, const int* in_sizes, int n_in,
                              void* d_out, int out_size)
{
    const float* x     = (const float*)d_in[0];
    const float* x_dot = (const float*)d_in[1];
    const float* pos   = (const float*)d_in[2];
    const float* W     = (const float*)d_in[3];
    float* out = (float*)d_out;

    const int D = (int)(sqrt((double)in_sizes[3]) + 0.5);
    const int B = in_sizes[0] / D;
    const int P = in_sizes[2] / D;
    const int NS = D / BN;   // 8 N-slices

    __half *xh, *xl, *ph, *pl, *wh;
    float *xparts, *pparts, *ab;
    cudaGetSymbolAddress((void**)&xh, g_xh);
    cudaGetSymbolAddress((void**)&xl, g_xl);
    cudaGetSymbolAddress((void**)&ph, g_ph);
    cudaGetSymbolAddress((void**)&pl, g_pl);
    cudaGetSymbolAddress((void**)&wh, g_wh);
    cudaGetSymbolAddress((void**)&xparts, g_xparts);
    cudaGetSymbolAddress((void**)&pparts, g_pparts);
    cudaGetSymbolAddress((void**)&ab, g_ab);

    cudaFuncSetAttribute(mma_gemm_norm,
                         cudaFuncAttributeMaxDynamicSharedMemorySize, SMEM_TOTAL);

    // prep: fp16 hi/lo splits for rows, fp16 transpose for W
    {
        int n4 = (B * D) / 4;
        split_kernel<<<(n4 + 255) / 256, 256>>>(x, xh, xl, n4);
        int p4 = (P * D) / 4;
        split_kernel<<<(p4 + 255) / 256, 256>>>(pos, ph, pl, p4);
        wsplit_kernel<<<dim3(D / 32, D / 32), dim3(32, 8)>>>(W, wh, D);
    }

    // GEMM-norms (tensor cores via mma.sync, 2-term fp16)
    mma_gemm_norm<<<dim3(B / BM, NS), 256, SMEM_TOTAL>>>(xh, xl, wh, D, xparts, B);
    mma_gemm_norm<<<dim3(P / BM, NS), 256, SMEM_TOTAL>>>(ph, pl, wh, D, pparts, P);

    // alpha/beta
    calib_kernel<<<1, 256>>>(pparts, P, NS, ab);

    // fused rowsum(x_dot^2) + scale
    const int rows_per_block = 256 / 32;
    finalize_kernel<<<(B + rows_per_block - 1) / rows_per_block, 256>>>(
        x_dot, xparts, NS, ab, out, B, D);
}

// round 5
// speedup vs baseline: 9.7697x; 1.6317x over previous
#include <cuda_runtime.h>
#include <cuda_fp16.h>
#include <math.h>
#include <stdint.h>

// ===========================================================================
// ScoreMagnitudeMetric via warp-level mma.sync fp16 single-term GEMM:
//   scores = x @ W  ~=  fp16(x) @ fp16(W^T)   (fp32 accumulation)
//   Per-element quantization rel-err ~2.8e-4 on each operand averages to
//   ~1e-4 global through the norm^2/norm^4/alpha chain (model validated R3/R4:
//   W-only quantization measured 7.0e-5).
//   n2[b] = ||scores_b||^2 ; out[b] = (alpha*n2^2 + beta) * ||x_dot_b||^2
// ===========================================================================

#define MAXB 32768
#define MAXP 2048
#define MAXD 1024

#define BM 128
#define BN 128
#define BK 32
#define NSLICE_MAX (MAXD / BN)   // 8

// scratch (device globals; no allocation allowed)
__device__ __half g_xh[(size_t)MAXB * MAXD];
__device__ __half g_ph[(size_t)MAXP * MAXD];
__device__ __half g_wh[(size_t)MAXD * MAXD];   // fp16(W^T)
__device__ float g_xparts[NSLICE_MAX * MAXB];
__device__ float g_pparts[NSLICE_MAX * MAXP];
__device__ float g_ab[2];

// ---------------------------------------------------------------------------
// helpers
// ---------------------------------------------------------------------------
__device__ __forceinline__ uint32_t smem_to_u32(const void* p) {
    uint32_t a;
    asm("{ .reg .u64 t; cvta.to.shared.u64 t, %1; cvt.u32.u64 %0, t; }"
        : "=r"(a) : "l"(p));
    return a;
}

#define CP_ASYNC16(sm, g) \
    asm volatile("cp.async.cg.shared.global [%0], [%1], 16;" :: "r"(sm), "l"(g) : "memory")
#define CP_COMMIT()  asm volatile("cp.async.commit_group;" ::: "memory")
#define CP_WAIT2()   asm volatile("cp.async.wait_group 2;" ::: "memory")
#define CP_WAIT1()   asm volatile("cp.async.wait_group 1;" ::: "memory")
#define CP_WAIT0()   asm volatile("cp.async.wait_group 0;" ::: "memory")

__device__ __forceinline__ void ldsm_x4(uint32_t* r, uint32_t addr) {
    asm volatile("ldmatrix.sync.aligned.m8n8.x4.shared.b16 {%0,%1,%2,%3}, [%4];"
                 : "=r"(r[0]), "=r"(r[1]), "=r"(r[2]), "=r"(r[3]) : "r"(addr));
}

__device__ __forceinline__ void mma16816(float* c, const uint32_t* a,
                                         uint32_t b0, uint32_t b1) {
    asm volatile(
        "mma.sync.aligned.m16n8k16.row.col.f32.f16.f16.f32 "
        "{%0,%1,%2,%3}, {%4,%5,%6,%7}, {%8,%9}, {%0,%1,%2,%3};"
        : "+f"(c[0]), "+f"(c[1]), "+f"(c[2]), "+f"(c[3])
        : "r"(a[0]), "r"(a[1]), "r"(a[2]), "r"(a[3]), "r"(b0), "r"(b1));
}

// ---------------------------------------------------------------------------
// Prep: fp32 -> fp16 convert (vectorized by 4)
// ---------------------------------------------------------------------------
__global__ void cvt_kernel(const float* __restrict__ src,
                           __half* __restrict__ dst, int n4)
{
    int i = blockIdx.x * blockDim.x + threadIdx.x;
    if (i >= n4) return;
    float4 v = reinterpret_cast<const float4*>(src)[i];
    __half2* hp = reinterpret_cast<__half2*>(dst) + 2 * i;
    hp[0] = __half2(__float2half_rn(v.x), __float2half_rn(v.y));
    hp[1] = __half2(__float2half_rn(v.z), __float2half_rn(v.w));
}

// W [k][j] -> Wt [j][k] fp16 (32x32 smem transpose tiles)
__global__ void wsplit_kernel(const float* __restrict__ W,
                              __half* __restrict__ wth, int D)
{
    __shared__ float t[32][33];
    const int j0 = blockIdx.x * 32, k0 = blockIdx.y * 32;
    const int tx = threadIdx.x, ty = threadIdx.y;  // (32, 8)
    #pragma unroll
    for (int r = 0; r < 4; ++r)
        t[ty + 8 * r][tx] = W[(size_t)(k0 + ty + 8 * r) * D + j0 + tx];
    __syncthreads();
    #pragma unroll
    for (int r = 0; r < 4; ++r) {
        float v = t[tx][ty + 8 * r];
        wth[(size_t)(j0 + ty + 8 * r) * D + k0 + tx] = __float2half_rn(v);
    }
}

// ---------------------------------------------------------------------------
// mma.sync GEMM-norm, fp16 single-term.
// Block: 128 rows x 128 cols, K in 32-chunks, 4-stage cp.async pipeline with
// a single __syncthreads per chunk.  2 CTAs/SM (regs<=128, smem 80KB/CTA).
// Smem tile rows: 32 halves = 64 B data, 80 B stride (conflict-free ldmatrix).
// parts[blockIdx.y * rowStride + m] = sum of squares over this 128-col slice.
// ---------------------------------------------------------------------------
#define TILE_B   10240              // 128 rows * 80 B
#define A_OFF    0
#define B_OFF    (TILE_B)
#define STAGE_B  (2 * TILE_B)       // 20480
#define NSTAGE   4
#define SMEM_TOTAL (NSTAGE * STAGE_B)   // 81920

__global__ __launch_bounds__(256, 2)
void mma_gemm_norm(const __half* __restrict__ A,
                   const __half* __restrict__ Bm,
                   int D, float* __restrict__ parts, int rowStride)
{
    extern __shared__ __align__(128) char smem[];
    const uint32_t sm0 = smem_to_u32(smem);

    const int tid  = threadIdx.x;
    const int wid  = tid >> 5;
    const int lane = tid & 31;
    const int wm   = wid >> 2;          // 0..1  -> rows wm*64
    const int wn   = wid & 3;           // 0..3  -> cols wn*32
    const int m0   = blockIdx.x * BM;
    const int n0   = blockIdx.y * BN;
    const int KC   = D / BK;

    const __half* gA = A  + (size_t)m0 * D;
    const __half* gB = Bm + (size_t)n0 * D;

    float acc[4][4][4];
    #pragma unroll
    for (int i = 0; i < 4; ++i)
        #pragma unroll
        for (int j = 0; j < 4; ++j)
            #pragma unroll
            for (int c = 0; c < 4; ++c) acc[i][j][c] = 0.f;

    auto load_chunk = [&](int kc, int s) {
        const uint32_t sb = sm0 + (uint32_t)s * STAGE_B;
        const int kb = kc * BK;          // halves
        #pragma unroll
        for (int i = 0; i < 2; ++i) {
            int idx = tid + 256 * i;     // 0..511
            int r = idx >> 2, c = idx & 3;
            uint32_t so = (uint32_t)(r * 80 + c * 16);
            size_t go = (size_t)r * D + kb + c * 8;
            CP_ASYNC16(sb + A_OFF + so, gA + go);
            CP_ASYNC16(sb + B_OFF + so, gB + go);
        }
    };

    // ldmatrix per-lane address pieces
    const int a_row = (lane & 15);                         // + mrow + mt*16
    const int a_ku  = (lane >> 4);                         // + kub
    const int b_row = ((lane >> 4) << 3) + (lane & 7);     // + nrow + ng*16
    const int b_ku  = ((lane >> 3) & 1);                   // + kub
    const int mrow  = wm * 64;
    const int nrow  = wn * 32;

    // prologue: three chunks in flight
    load_chunk(0, 0);
    CP_COMMIT();
    load_chunk(1, 1);
    CP_COMMIT();
    load_chunk(2, 2);
    CP_COMMIT();

    for (int kc = 0; kc < KC; ++kc) {
        const int s = kc % NSTAGE;
        // groups newer than kc currently pending: min(kc+2, KC-1) - kc
        if (kc + 2 <= KC - 1)      CP_WAIT2();
        else if (kc + 1 <= KC - 1) CP_WAIT1();
        else                       CP_WAIT0();
        __syncthreads();      // data(kc) visible; stage (kc+3)%4 free (compute
                              // of chunk kc-1 finished before this barrier)
        if (kc + 3 < KC) {
            load_chunk(kc + 3, (kc + 3) % NSTAGE);
            CP_COMMIT();
        }

        const uint32_t sb = sm0 + (uint32_t)s * STAGE_B;
        #pragma unroll
        for (int ks = 0; ks < 2; ++ks) {        // two k16 steps per chunk
            const int kub = ks * 2;
            uint32_t ah[4][4], bh[2][4];
            #pragma unroll
            for (int mt = 0; mt < 4; ++mt) {
                uint32_t off = (uint32_t)((mrow + mt * 16 + a_row) * 80
                                          + (kub + a_ku) * 16);
                ldsm_x4(ah[mt], sb + A_OFF + off);
            }
            #pragma unroll
            for (int ng = 0; ng < 2; ++ng) {
                uint32_t off = (uint32_t)((nrow + ng * 16 + b_row) * 80
                                          + (kub + b_ku) * 16);
                ldsm_x4(bh[ng], sb + B_OFF + off);
            }
            #pragma unroll
            for (int mt = 0; mt < 4; ++mt) {
                #pragma unroll
                for (int nt = 0; nt < 4; ++nt) {
                    uint32_t b0 = bh[nt >> 1][2 * (nt & 1)];
                    uint32_t b1 = bh[nt >> 1][2 * (nt & 1) + 1];
                    mma16816(acc[mt][nt], ah[mt], b0, b1);
                }
            }
        }
    }
    __syncthreads();   // all compute done before smem reuse below

    // ---- epilogue: row-wise sum of squares -------------------------------
    // acc c0,c1 -> row (lane>>2); c2,c3 -> row (lane>>2)+8 within each m16.
    float* rbuf = reinterpret_cast<float*>(smem);   // [128][4]
    float rs0[4], rs1[4];
    #pragma unroll
    for (int mt = 0; mt < 4; ++mt) {
        float s0 = 0.f, s1 = 0.f;
        #pragma unroll
        for (int nt = 0; nt < 4; ++nt) {
            s0 += acc[mt][nt][0] * acc[mt][nt][0] + acc[mt][nt][1] * acc[mt][nt][1];
            s1 += acc[mt][nt][2] * acc[mt][nt][2] + acc[mt][nt][3] * acc[mt][nt][3];
        }
        s0 += __shfl_xor_sync(0xFFFFFFFFu, s0, 1);
        s0 += __shfl_xor_sync(0xFFFFFFFFu, s0, 2);
        s1 += __shfl_xor_sync(0xFFFFFFFFu, s1, 1);
        s1 += __shfl_xor_sync(0xFFFFFFFFu, s1, 2);
        rs0[mt] = s0;
        rs1[mt] = s1;
    }
    if ((lane & 3) == 0) {
        int rq = lane >> 2;      // 0..7
        #pragma unroll
        for (int mt = 0; mt < 4; ++mt) {
            int row = mrow + mt * 16 + rq;
            rbuf[row * 4 + wn] = rs0[mt];
            rbuf[(row + 8) * 4 + wn] = rs1[mt];
        }
    }
    __syncthreads();
    if (tid < BM) {
        float tot = rbuf[tid * 4 + 0] + rbuf[tid * 4 + 1]
                  + rbuf[tid * 4 + 2] + rbuf[tid * 4 + 3];
        parts[(size_t)blockIdx.y * rowStride + m0 + tid] = tot;
    }
}

// ---------------------------------------------------------------------------
// Calibration: n2 = sum of N-slice partials; n4 = n2^2; alpha/beta from max/min
// ---------------------------------------------------------------------------
__global__ void calib_kernel(const float* __restrict__ parts, int P, int nparts,
                             float* __restrict__ ab)
{
    __shared__ float smx[256], smn[256];
    const int tid = threadIdx.x;
    float mx = -1e30f, mn = 1e30f;
    for (int r = tid; r < P; r += 256) {
        float tot = 0.f;
        for (int y = 0; y < nparts; ++y) tot += parts[(size_t)y * P + r];
        float n4 = tot * tot;
        mx = fmaxf(mx, n4);
        mn = fminf(mn, n4);
    }
    smx[tid] = mx; smn[tid] = mn;
    __syncthreads();
    for (int s = 128; s > 0; s >>= 1) {
        if (tid < s) {
            smx[tid] = fmaxf(smx[tid], smx[tid + s]);
            smn[tid] = fminf(smn[tid], smn[tid + s]);
        }
        __syncthreads();
    }
    if (tid == 0) {
        float alpha = (1.0f - 0.001f) / (smx[0] - smn[0]);
        ab[0] = alpha;
        ab[1] = 0.001f - alpha * smn[0];
    }
}

// ---------------------------------------------------------------------------
// Finalize: warp per row; n2 from N-slice partials; out = (a*n2^2+b)*||xd||^2
// ---------------------------------------------------------------------------
__global__ __launch_bounds__(256)
void finalize_kernel(const float* __restrict__ x_dot,
                     const float* __restrict__ parts, int nparts,
                     const float* __restrict__ ab,
                     float* __restrict__ out, int B, int D)
{
    const int warp = (blockIdx.x * blockDim.x + threadIdx.x) >> 5;
    const int lane = threadIdx.x & 31;
    if (warp >= B) return;

    const int D4 = D >> 2;
    const float4* xd = reinterpret_cast<const float4*>(x_dot) + (size_t)warp * D4;
    float s = 0.f;
    for (int i = lane; i < D4; i += 32) {
        float4 v = xd[i];
        s += v.x * v.x + v.y * v.y + v.z * v.z + v.w * v.w;
    }
    #pragma unroll
    for (int off = 16; off > 0; off >>= 1)
        s += __shfl_down_sync(0xFFFFFFFFu, s, off);

    if (lane == 0) {
        float n2 = 0.f;
        for (int y = 0; y < nparts; ++y) n2 += parts[(size_t)y * B + warp];
        float a = ab[0], b = ab[1];
        out[warp] = (a * n2 * n2 + b) * s;
    }
}

// ---------------------------------------------------------------------------
// kernel_launch
// ---------------------------------------------------------------------------
extern "C" void kernel_launch(void* const* d_in, const int* in_sizes, int n_in,
                              void* d_out, int out_size)
{
    const float* x     = (const float*)d_in[0];
    const float* x_dot = (const float*)d_in[1];
    const float* pos   = (const float*)d_in[2];
    const float* W     = (const float*)d_in[3];
    float* out = (float*)d_out;

    const int D = (int)(sqrt((double)in_sizes[3]) + 0.5);
    const int B = in_sizes[0] / D;
    const int P = in_sizes[2] / D;
    const int NS = D / BN;   // 8 N-slices

    __half *xh, *ph, *wh;
    float *xparts, *pparts, *ab;
    cudaGetSymbolAddress((void**)&xh, g_xh);
    cudaGetSymbolAddress((void**)&ph, g_ph);
    cudaGetSymbolAddress((void**)&wh, g_wh);
    cudaGetSymbolAddress((void**)&xparts, g_xparts);
    cudaGetSymbolAddress((void**)&pparts, g_pparts);
    cudaGetSymbolAddress((void**)&ab, g_ab);

    cudaFuncSetAttribute(mma_gemm_norm,
                         cudaFuncAttributeMaxDynamicSharedMemorySize, SMEM_TOTAL);

    // prep: fp16 converts for rows, fp16 transpose for W
    {
        int n4 = (B * D) / 4;
        cvt_kernel<<<(n4 + 255) / 256, 256>>>(x, xh, n4);
        int p4 = (P * D) / 4;
        cvt_kernel<<<(p4 + 255) / 256, 256>>>(pos, ph, p4);
        wsplit_kernel<<<dim3(D / 32, D / 32), dim3(32, 8)>>>(W, wh, D);
    }

    // GEMM-norms (tensor cores via mma.sync, single-term fp16)
    mma_gemm_norm<<<dim3(B / BM, NS), 256, SMEM_TOTAL>>>(xh, wh, D, xparts, B);
    mma_gemm_norm<<<dim3(P / BM, NS), 256, SMEM_TOTAL>>>(ph, wh, D, pparts, P);

    // alpha/beta
    calib_kernel<<<1, 256>>>(pparts, P, NS, ab);

    // fused rowsum(x_dot^2) + scale
    const int rows_per_block = 256 / 32;
    finalize_kernel<<<(B + rows_per_block - 1) / rows_per_block, 256>>>(
        x_dot, xparts, NS, ab, out, B, D);
}

// round 6
// speedup vs baseline: 10.4531x; 1.0700x over previous
#include <cuda_runtime.h>
#include <cuda_fp16.h>
#include <math.h>
#include <stdint.h>

// ===========================================================================
// ScoreMagnitudeMetric via warp-level mma.sync fp16 single-term GEMM:
//   scores = x @ W  ~=  fp16(x) @ fp16(W^T)   (fp32 accumulation)
//   n2[b] = ||scores_b||^2 ; out[b] = (alpha*n2^2 + beta) * ||x_dot_b||^2
// R6: BK=64 chunks (half the syncs, deeper ILP), x+pos gemms merged into one
// launch. Smem rows 144B stride (gcd(9,8)=1 -> conflict-free ldmatrix).
// ===========================================================================

#define MAXB 32768
#define MAXP 2048
#define MAXD 1024

#define BM 128
#define BN 128
#define BK 64
#define NSLICE_MAX (MAXD / BN)   // 8

// scratch (device globals; no allocation allowed)
__device__ __half g_xh[(size_t)MAXB * MAXD];
__device__ __half g_ph[(size_t)MAXP * MAXD];
__device__ __half g_wh[(size_t)MAXD * MAXD];   // fp16(W^T)
__device__ float g_xparts[NSLICE_MAX * MAXB];
__device__ float g_pparts[NSLICE_MAX * MAXP];
__device__ float g_ab[2];

// ---------------------------------------------------------------------------
// helpers
// ---------------------------------------------------------------------------
__device__ __forceinline__ uint32_t smem_to_u32(const void* p) {
    uint32_t a;
    asm("{ .reg .u64 t; cvta.to.shared.u64 t, %1; cvt.u32.u64 %0, t; }"
        : "=r"(a) : "l"(p));
    return a;
}

#define CP_ASYNC16(sm, g) \
    asm volatile("cp.async.cg.shared.global [%0], [%1], 16;" :: "r"(sm), "l"(g) : "memory")
#define CP_COMMIT()  asm volatile("cp.async.commit_group;" ::: "memory")
#define CP_WAIT1()   asm volatile("cp.async.wait_group 1;" ::: "memory")
#define CP_WAIT0()   asm volatile("cp.async.wait_group 0;" ::: "memory")

__device__ __forceinline__ void ldsm_x4(uint32_t* r, uint32_t addr) {
    asm volatile("ldmatrix.sync.aligned.m8n8.x4.shared.b16 {%0,%1,%2,%3}, [%4];"
                 : "=r"(r[0]), "=r"(r[1]), "=r"(r[2]), "=r"(r[3]) : "r"(addr));
}

__device__ __forceinline__ void mma16816(float* c, const uint32_t* a,
                                         uint32_t b0, uint32_t b1) {
    asm volatile(
        "mma.sync.aligned.m16n8k16.row.col.f32.f16.f16.f32 "
        "{%0,%1,%2,%3}, {%4,%5,%6,%7}, {%8,%9}, {%0,%1,%2,%3};"
        : "+f"(c[0]), "+f"(c[1]), "+f"(c[2]), "+f"(c[3])
        : "r"(a[0]), "r"(a[1]), "r"(a[2]), "r"(a[3]), "r"(b0), "r"(b1));
}

// ---------------------------------------------------------------------------
// Prep: fp32 -> fp16 convert (vectorized by 4)
// ---------------------------------------------------------------------------
__global__ void cvt_kernel(const float* __restrict__ src,
                           __half* __restrict__ dst, int n4)
{
    int i = blockIdx.x * blockDim.x + threadIdx.x;
    if (i >= n4) return;
    float4 v = reinterpret_cast<const float4*>(src)[i];
    __half2* hp = reinterpret_cast<__half2*>(dst) + 2 * i;
    hp[0] = __half2(__float2half_rn(v.x), __float2half_rn(v.y));
    hp[1] = __half2(__float2half_rn(v.z), __float2half_rn(v.w));
}

// W [k][j] -> Wt [j][k] fp16 (32x32 smem transpose tiles)
__global__ void wsplit_kernel(const float* __restrict__ W,
                              __half* __restrict__ wth, int D)
{
    __shared__ float t[32][33];
    const int j0 = blockIdx.x * 32, k0 = blockIdx.y * 32;
    const int tx = threadIdx.x, ty = threadIdx.y;  // (32, 8)
    #pragma unroll
    for (int r = 0; r < 4; ++r)
        t[ty + 8 * r][tx] = W[(size_t)(k0 + ty + 8 * r) * D + j0 + tx];
    __syncthreads();
    #pragma unroll
    for (int r = 0; r < 4; ++r) {
        float v = t[tx][ty + 8 * r];
        wth[(size_t)(j0 + ty + 8 * r) * D + k0 + tx] = __float2half_rn(v);
    }
}

// ---------------------------------------------------------------------------
// mma.sync GEMM-norm, fp16 single-term.  x and pos handled in ONE launch:
//   blockIdx.x <  nxB : rows of X  -> xparts (stride Brows)
//   blockIdx.x >= nxB : rows of Pm -> pparts (stride Prows)
// Block: 128 rows x 128 cols, K in 64-chunks, 3-stage cp.async pipeline,
// single __syncthreads per chunk.  2 CTAs/SM (regs<=128, smem 108KB/CTA).
// Smem tile rows: 64 halves = 128 B data, 144 B stride.
// ---------------------------------------------------------------------------
#define TILE_B   18432              // 128 rows * 144 B
#define A_OFF    0
#define B_OFF    (TILE_B)
#define STAGE_B  (2 * TILE_B)       // 36864
#define NSTAGE   3
#define SMEM_TOTAL (NSTAGE * STAGE_B)   // 110592

__global__ __launch_bounds__(256, 2)
void mma_gemm_norm(const __half* __restrict__ X,
                   const __half* __restrict__ Pm,
                   const __half* __restrict__ Wm,
                   int D, int nxB,
                   float* __restrict__ xparts, int Brows,
                   float* __restrict__ pparts, int Prows)
{
    extern __shared__ __align__(128) char smem[];
    const uint32_t sm0 = smem_to_u32(smem);

    const int tid  = threadIdx.x;
    const int wid  = tid >> 5;
    const int lane = tid & 31;
    const int wm   = wid >> 2;          // 0..1  -> rows wm*64
    const int wn   = wid & 3;           // 0..3  -> cols wn*32
    const int KC   = D / BK;            // 16

    const bool isX = ((int)blockIdx.x < nxB);
    const int  mb  = isX ? (int)blockIdx.x : (int)blockIdx.x - nxB;
    const int  m0  = mb * BM;
    const int  n0  = blockIdx.y * BN;
    float* parts   = isX ? xparts : pparts;
    const int rowStride = isX ? Brows : Prows;

    const __half* gA = (isX ? X : Pm) + (size_t)m0 * D;
    const __half* gB = Wm + (size_t)n0 * D;

    float acc[4][4][4];
    #pragma unroll
    for (int i = 0; i < 4; ++i)
        #pragma unroll
        for (int j = 0; j < 4; ++j)
            #pragma unroll
            for (int c = 0; c < 4; ++c) acc[i][j][c] = 0.f;

    auto load_chunk = [&](int kc, int s) {
        const uint32_t sb = sm0 + (uint32_t)s * STAGE_B;
        const int kb = kc * BK;          // halves
        #pragma unroll
        for (int i = 0; i < 4; ++i) {
            int idx = tid + 256 * i;     // 0..1023
            int r = idx >> 3, c = idx & 7;
            uint32_t so = (uint32_t)(r * 144 + c * 16);
            size_t go = (size_t)r * D + kb + c * 8;
            CP_ASYNC16(sb + A_OFF + so, gA + go);
            CP_ASYNC16(sb + B_OFF + so, gB + go);
        }
    };

    // ldmatrix per-lane address pieces
    const int a_row = (lane & 15);                         // + mrow + mt*16
    const int a_ku  = (lane >> 4);                         // + kub
    const int b_row = ((lane >> 4) << 3) + (lane & 7);     // + nrow + ng*16
    const int b_ku  = ((lane >> 3) & 1);                   // + kub
    const int mrow  = wm * 64;
    const int nrow  = wn * 32;

    // prologue: two chunks in flight
    load_chunk(0, 0);
    CP_COMMIT();
    load_chunk(1, 1);
    CP_COMMIT();

    for (int kc = 0; kc < KC; ++kc) {
        const int s = kc % NSTAGE;
        if (kc + 1 <= KC - 1) CP_WAIT1(); else CP_WAIT0();
        __syncthreads();      // load(kc) visible; stage (kc+2)%3 free (its
                              // reader, compute(kc-1), finished pre-barrier)
        if (kc + 2 < KC) {
            load_chunk(kc + 2, (kc + 2) % NSTAGE);
            CP_COMMIT();
        }

        const uint32_t sb = sm0 + (uint32_t)s * STAGE_B;
        #pragma unroll
        for (int ks = 0; ks < 4; ++ks) {        // four k16 steps per chunk
            const int kub = ks * 2;
            uint32_t ah[4][4], bh[2][4];
            #pragma unroll
            for (int mt = 0; mt < 4; ++mt) {
                uint32_t off = (uint32_t)((mrow + mt * 16 + a_row) * 144
                                          + (kub + a_ku) * 16);
                ldsm_x4(ah[mt], sb + A_OFF + off);
            }
            #pragma unroll
            for (int ng = 0; ng < 2; ++ng) {
                uint32_t off = (uint32_t)((nrow + ng * 16 + b_row) * 144
                                          + (kub + b_ku) * 16);
                ldsm_x4(bh[ng], sb + B_OFF + off);
            }
            #pragma unroll
            for (int mt = 0; mt < 4; ++mt) {
                #pragma unroll
                for (int nt = 0; nt < 4; ++nt) {
                    uint32_t b0 = bh[nt >> 1][2 * (nt & 1)];
                    uint32_t b1 = bh[nt >> 1][2 * (nt & 1) + 1];
                    mma16816(acc[mt][nt], ah[mt], b0, b1);
                }
            }
        }
    }
    __syncthreads();   // all compute done before smem reuse below

    // ---- epilogue: row-wise sum of squares -------------------------------
    // acc c0,c1 -> row (lane>>2); c2,c3 -> row (lane>>2)+8 within each m16.
    float* rbuf = reinterpret_cast<float*>(smem);   // [128][4]
    float rs0[4], rs1[4];
    #pragma unroll
    for (int mt = 0; mt < 4; ++mt) {
        float s0 = 0.f, s1 = 0.f;
        #pragma unroll
        for (int nt = 0; nt < 4; ++nt) {
            s0 += acc[mt][nt][0] * acc[mt][nt][0] + acc[mt][nt][1] * acc[mt][nt][1];
            s1 += acc[mt][nt][2] * acc[mt][nt][2] + acc[mt][nt][3] * acc[mt][nt][3];
        }
        s0 += __shfl_xor_sync(0xFFFFFFFFu, s0, 1);
        s0 += __shfl_xor_sync(0xFFFFFFFFu, s0, 2);
        s1 += __shfl_xor_sync(0xFFFFFFFFu, s1, 1);
        s1 += __shfl_xor_sync(0xFFFFFFFFu, s1, 2);
        rs0[mt] = s0;
        rs1[mt] = s1;
    }
    if ((lane & 3) == 0) {
        int rq = lane >> 2;      // 0..7
        #pragma unroll
        for (int mt = 0; mt < 4; ++mt) {
            int row = mrow + mt * 16 + rq;
            rbuf[row * 4 + wn] = rs0[mt];
            rbuf[(row + 8) * 4 + wn] = rs1[mt];
        }
    }
    __syncthreads();
    if (tid < BM) {
        float tot = rbuf[tid * 4 + 0] + rbuf[tid * 4 + 1]
                  + rbuf[tid * 4 + 2] + rbuf[tid * 4 + 3];
        parts[(size_t)blockIdx.y * rowStride + m0 + tid] = tot;
    }
}

// ---------------------------------------------------------------------------
// Calibration: n2 = sum of N-slice partials; n4 = n2^2; alpha/beta from max/min
// ---------------------------------------------------------------------------
__global__ void calib_kernel(const float* __restrict__ parts, int P, int nparts,
                             float* __restrict__ ab)
{
    __shared__ float smx[256], smn[256];
    const int tid = threadIdx.x;
    float mx = -1e30f, mn = 1e30f;
    for (int r = tid; r < P; r += 256) {
        float tot = 0.f;
        for (int y = 0; y < nparts; ++y) tot += parts[(size_t)y * P + r];
        float n4 = tot * tot;
        mx = fmaxf(mx, n4);
        mn = fminf(mn, n4);
    }
    smx[tid] = mx; smn[tid] = mn;
    __syncthreads();
    for (int s = 128; s > 0; s >>= 1) {
        if (tid < s) {
            smx[tid] = fmaxf(smx[tid], smx[tid + s]);
            smn[tid] = fminf(smn[tid], smn[tid + s]);
        }
        __syncthreads();
    }
    if (tid == 0) {
        float alpha = (1.0f - 0.001f) / (smx[0] - smn[0]);
        ab[0] = alpha;
        ab[1] = 0.001f - alpha * smn[0];
    }
}

// ---------------------------------------------------------------------------
// Finalize: warp per row; n2 from N-slice partials; out = (a*n2^2+b)*||xd||^2
// ---------------------------------------------------------------------------
__global__ __launch_bounds__(256)
void finalize_kernel(const float* __restrict__ x_dot,
                     const float* __restrict__ parts, int nparts,
                     const float* __restrict__ ab,
                     float* __restrict__ out, int B, int D)
{
    const int warp = (blockIdx.x * blockDim.x + threadIdx.x) >> 5;
    const int lane = threadIdx.x & 31;
    if (warp >= B) return;

    const int D4 = D >> 2;
    const float4* xd = reinterpret_cast<const float4*>(x_dot) + (size_t)warp * D4;
    float s = 0.f;
    for (int i = lane; i < D4; i += 32) {
        float4 v = xd[i];
        s += v.x * v.x + v.y * v.y + v.z * v.z + v.w * v.w;
    }
    #pragma unroll
    for (int off = 16; off > 0; off >>= 1)
        s += __shfl_down_sync(0xFFFFFFFFu, s, off);

    if (lane == 0) {
        float n2 = 0.f;
        for (int y = 0; y < nparts; ++y) n2 += parts[(size_t)y * B + warp];
        float a = ab[0], b = ab[1];
        out[warp] = (a * n2 * n2 + b) * s;
    }
}

// ---------------------------------------------------------------------------
// kernel_launch
// ---------------------------------------------------------------------------
extern "C" void kernel_launch(void* const* d_in, const int* in_sizes, int n_in,
                              void* d_out, int out_size)
{
    const float* x     = (const float*)d_in[0];
    const float* x_dot = (const float*)d_in[1];
    const float* pos   = (const float*)d_in[2];
    const float* W     = (const float*)d_in[3];
    float* out = (float*)d_out;

    const int D = (int)(sqrt((double)in_sizes[3]) + 0.5);
    const int B = in_sizes[0] / D;
    const int P = in_sizes[2] / D;
    const int NS = D / BN;   // 8 N-slices

    __half *xh, *ph, *wh;
    float *xparts, *pparts, *ab;
    cudaGetSymbolAddress((void**)&xh, g_xh);
    cudaGetSymbolAddress((void**)&ph, g_ph);
    cudaGetSymbolAddress((void**)&wh, g_wh);
    cudaGetSymbolAddress((void**)&xparts, g_xparts);
    cudaGetSymbolAddress((void**)&pparts, g_pparts);
    cudaGetSymbolAddress((void**)&ab, g_ab);

    cudaFuncSetAttribute(mma_gemm_norm,
                         cudaFuncAttributeMaxDynamicSharedMemorySize, SMEM_TOTAL);

    // prep: fp16 converts for rows, fp16 transpose for W
    {
        int n4 = (B * D) / 4;
        cvt_kernel<<<(n4 + 255) / 256, 256>>>(x, xh, n4);
        int p4 = (P * D) / 4;
        cvt_kernel<<<(p4 + 255) / 256, 256>>>(pos, ph, p4);
        wsplit_kernel<<<dim3(D / 32, D / 32), dim3(32, 8)>>>(W, wh, D);
    }

    // merged x + pos GEMM-norms (single launch)
    const int nxB = B / BM;
    const int npB = P / BM;
    mma_gemm_norm<<<dim3(nxB + npB, NS), 256, SMEM_TOTAL>>>(
        xh, ph, wh, D, nxB, xparts, B, pparts, P);

    // alpha/beta
    calib_kernel<<<1, 256>>>(pparts, P, NS, ab);

    // fused rowsum(x_dot^2) + scale
    const int rows_per_block = 256 / 32;
    finalize_kernel<<<(B + rows_per_block - 1) / rows_per_block, 256>>>(
        x_dot, xparts, NS, ab, out, B, D);
}

// round 7
// speedup vs baseline: 10.8283x; 1.0359x over previous
#include <cuda_runtime.h>
#include <cuda_fp16.h>
#include <math.h>
#include <stdint.h>

// ===========================================================================
// ScoreMagnitudeMetric via warp-level mma.sync fp16 single-term GEMM:
//   scores = x @ W  ~=  fp16(x) @ fp16(W^T)   (fp32 accumulation)
//   n2[b] = ||scores_b||^2 ; out[b] = (alpha*n2^2 + beta) * ||x_dot_b||^2
// R7: 64x64 warp tiles (4 warps / 128 threads per block) -> LDSM fragment
// traffic per HMMA drops 1.5x; crossbar no longer co-critical with tensor.
// ===========================================================================

#define MAXB 32768
#define MAXP 2048
#define MAXD 1024

#define BM 128
#define BN 128
#define BK 64
#define NSLICE_MAX (MAXD / BN)   // 8

// scratch (device globals; no allocation allowed)
__device__ __half g_xh[(size_t)MAXB * MAXD];
__device__ __half g_ph[(size_t)MAXP * MAXD];
__device__ __half g_wh[(size_t)MAXD * MAXD];   // fp16(W^T)
__device__ float g_xparts[NSLICE_MAX * MAXB];
__device__ float g_pparts[NSLICE_MAX * MAXP];
__device__ float g_ab[2];

// ---------------------------------------------------------------------------
// helpers
// ---------------------------------------------------------------------------
__device__ __forceinline__ uint32_t smem_to_u32(const void* p) {
    uint32_t a;
    asm("{ .reg .u64 t; cvta.to.shared.u64 t, %1; cvt.u32.u64 %0, t; }"
        : "=r"(a) : "l"(p));
    return a;
}

#define CP_ASYNC16(sm, g) \
    asm volatile("cp.async.cg.shared.global [%0], [%1], 16;" :: "r"(sm), "l"(g) : "memory")
#define CP_COMMIT()  asm volatile("cp.async.commit_group;" ::: "memory")
#define CP_WAIT1()   asm volatile("cp.async.wait_group 1;" ::: "memory")
#define CP_WAIT0()   asm volatile("cp.async.wait_group 0;" ::: "memory")

__device__ __forceinline__ void ldsm_x4(uint32_t* r, uint32_t addr) {
    asm volatile("ldmatrix.sync.aligned.m8n8.x4.shared.b16 {%0,%1,%2,%3}, [%4];"
                 : "=r"(r[0]), "=r"(r[1]), "=r"(r[2]), "=r"(r[3]) : "r"(addr));
}

__device__ __forceinline__ void mma16816(float* c, const uint32_t* a,
                                         uint32_t b0, uint32_t b1) {
    asm volatile(
        "mma.sync.aligned.m16n8k16.row.col.f32.f16.f16.f32 "
        "{%0,%1,%2,%3}, {%4,%5,%6,%7}, {%8,%9}, {%0,%1,%2,%3};"
        : "+f"(c[0]), "+f"(c[1]), "+f"(c[2]), "+f"(c[3])
        : "r"(a[0]), "r"(a[1]), "r"(a[2]), "r"(a[3]), "r"(b0), "r"(b1));
}

// ---------------------------------------------------------------------------
// Prep: fp32 -> fp16 convert (vectorized by 4)
// ---------------------------------------------------------------------------
__global__ void cvt_kernel(const float* __restrict__ src,
                           __half* __restrict__ dst, int n4)
{
    int i = blockIdx.x * blockDim.x + threadIdx.x;
    if (i >= n4) return;
    float4 v = reinterpret_cast<const float4*>(src)[i];
    __half2* hp = reinterpret_cast<__half2*>(dst) + 2 * i;
    hp[0] = __half2(__float2half_rn(v.x), __float2half_rn(v.y));
    hp[1] = __half2(__float2half_rn(v.z), __float2half_rn(v.w));
}

// W [k][j] -> Wt [j][k] fp16 (32x32 smem transpose tiles)
__global__ void wsplit_kernel(const float* __restrict__ W,
                              __half* __restrict__ wth, int D)
{
    __shared__ float t[32][33];
    const int j0 = blockIdx.x * 32, k0 = blockIdx.y * 32;
    const int tx = threadIdx.x, ty = threadIdx.y;  // (32, 8)
    #pragma unroll
    for (int r = 0; r < 4; ++r)
        t[ty + 8 * r][tx] = W[(size_t)(k0 + ty + 8 * r) * D + j0 + tx];
    __syncthreads();
    #pragma unroll
    for (int r = 0; r < 4; ++r) {
        float v = t[tx][ty + 8 * r];
        wth[(size_t)(j0 + ty + 8 * r) * D + k0 + tx] = __float2half_rn(v);
    }
}

// ---------------------------------------------------------------------------
// mma.sync GEMM-norm, fp16 single-term, 64x64 warp tiles.
//   blockIdx.x <  nxB : rows of X  -> xparts ;  else rows of Pm -> pparts
// Block: 128 rows x 128 cols, 4 warps (2x2 of 64x64), 128 threads.
// K in 64-chunks, 3-stage cp.async pipeline, one __syncthreads per chunk.
// 2 CTAs/SM (smem 108KB/CTA, regs <= 256).
// Smem tile rows: 64 halves = 128 B data, 144 B stride (conflict-free ldsm).
// ---------------------------------------------------------------------------
#define TILE_B   18432              // 128 rows * 144 B
#define A_OFF    0
#define B_OFF    (TILE_B)
#define STAGE_B  (2 * TILE_B)       // 36864
#define NSTAGE   3
#define SMEM_TOTAL (NSTAGE * STAGE_B)   // 110592

__global__ __launch_bounds__(128, 2)
void mma_gemm_norm(const __half* __restrict__ X,
                   const __half* __restrict__ Pm,
                   const __half* __restrict__ Wm,
                   int D, int nxB,
                   float* __restrict__ xparts, int Brows,
                   float* __restrict__ pparts, int Prows)
{
    extern __shared__ __align__(128) char smem[];
    const uint32_t sm0 = smem_to_u32(smem);

    const int tid  = threadIdx.x;
    const int wid  = tid >> 5;
    const int lane = tid & 31;
    const int wm   = wid >> 1;          // 0..1  -> rows wm*64
    const int wn   = wid & 1;           // 0..1  -> cols wn*64
    const int KC   = D / BK;            // 16

    const bool isX = ((int)blockIdx.x < nxB);
    const int  mb  = isX ? (int)blockIdx.x : (int)blockIdx.x - nxB;
    const int  m0  = mb * BM;
    const int  n0  = blockIdx.y * BN;
    float* parts   = isX ? xparts : pparts;
    const int rowStride = isX ? Brows : Prows;

    const __half* gA = (isX ? X : Pm) + (size_t)m0 * D;
    const __half* gB = Wm + (size_t)n0 * D;

    float acc[4][8][4];
    #pragma unroll
    for (int i = 0; i < 4; ++i)
        #pragma unroll
        for (int j = 0; j < 8; ++j)
            #pragma unroll
            for (int c = 0; c < 4; ++c) acc[i][j][c] = 0.f;

    auto load_chunk = [&](int kc, int s) {
        const uint32_t sb = sm0 + (uint32_t)s * STAGE_B;
        const int kb = kc * BK;          // halves
        #pragma unroll
        for (int i = 0; i < 8; ++i) {
            int idx = tid + 128 * i;     // 0..1023
            int r = idx >> 3, c = idx & 7;
            uint32_t so = (uint32_t)(r * 144 + c * 16);
            size_t go = (size_t)r * D + kb + c * 8;
            CP_ASYNC16(sb + A_OFF + so, gA + go);
            CP_ASYNC16(sb + B_OFF + so, gB + go);
        }
    };

    // ldmatrix per-lane address pieces (within-warp), hoisted
    const int a_row = (lane & 15);                         // + mrow + mt*16
    const int a_ku  = (lane >> 4);                         // + kub
    const int b_row = ((lane >> 4) << 3) + (lane & 7);     // + nrow + ng*16
    const int b_ku  = ((lane >> 3) & 1);                   // + kub
    const int mrow  = wm * 64;
    const int nrow  = wn * 64;
    const uint32_t aBase0 = (uint32_t)((mrow + a_row) * 144 + a_ku * 16);
    const uint32_t bBase0 = (uint32_t)((nrow + b_row) * 144 + b_ku * 16);

    // prologue: two chunks in flight
    load_chunk(0, 0);
    CP_COMMIT();
    load_chunk(1, 1);
    CP_COMMIT();

    for (int kc = 0; kc < KC; ++kc) {
        const int s = kc % NSTAGE;
        if (kc + 1 <= KC - 1) CP_WAIT1(); else CP_WAIT0();
        __syncthreads();      // load(kc) visible; stage (kc+2)%3 free
        if (kc + 2 < KC) {
            load_chunk(kc + 2, (kc + 2) % NSTAGE);
            CP_COMMIT();
        }

        const uint32_t sb = sm0 + (uint32_t)s * STAGE_B;
        const uint32_t aB = sb + A_OFF + aBase0;
        const uint32_t bB = sb + B_OFF + bBase0;
        #pragma unroll
        for (int ks = 0; ks < 4; ++ks) {        // four k16 steps per chunk
            const uint32_t kOff = (uint32_t)(ks * 32);   // kub*16
            uint32_t ah[4][4], bh[4][4];
            #pragma unroll
            for (int mt = 0; mt < 4; ++mt)
                ldsm_x4(ah[mt], aB + kOff + (uint32_t)(mt * 16 * 144));
            #pragma unroll
            for (int ng = 0; ng < 4; ++ng)
                ldsm_x4(bh[ng], bB + kOff + (uint32_t)(ng * 16 * 144));
            #pragma unroll
            for (int mt = 0; mt < 4; ++mt) {
                #pragma unroll
                for (int nt = 0; nt < 8; ++nt) {
                    uint32_t b0 = bh[nt >> 1][2 * (nt & 1)];
                    uint32_t b1 = bh[nt >> 1][2 * (nt & 1) + 1];
                    mma16816(acc[mt][nt], ah[mt], b0, b1);
                }
            }
        }
    }
    __syncthreads();   // all compute done before smem reuse below

    // ---- epilogue: row-wise sum of squares -------------------------------
    // acc c0,c1 -> row (lane>>2); c2,c3 -> row (lane>>2)+8 within each m16.
    float* rbuf = reinterpret_cast<float*>(smem);   // [128][2]
    float rs0[4], rs1[4];
    #pragma unroll
    for (int mt = 0; mt < 4; ++mt) {
        float s0 = 0.f, s1 = 0.f;
        #pragma unroll
        for (int nt = 0; nt < 8; ++nt) {
            s0 += acc[mt][nt][0] * acc[mt][nt][0] + acc[mt][nt][1] * acc[mt][nt][1];
            s1 += acc[mt][nt][2] * acc[mt][nt][2] + acc[mt][nt][3] * acc[mt][nt][3];
        }
        s0 += __shfl_xor_sync(0xFFFFFFFFu, s0, 1);
        s0 += __shfl_xor_sync(0xFFFFFFFFu, s0, 2);
        s1 += __shfl_xor_sync(0xFFFFFFFFu, s1, 1);
        s1 += __shfl_xor_sync(0xFFFFFFFFu, s1, 2);
        rs0[mt] = s0;
        rs1[mt] = s1;
    }
    if ((lane & 3) == 0) {
        int rq = lane >> 2;      // 0..7
        #pragma unroll
        for (int mt = 0; mt < 4; ++mt) {
            int row = mrow + mt * 16 + rq;
            rbuf[row * 2 + wn] = rs0[mt];
            rbuf[(row + 8) * 2 + wn] = rs1[mt];
        }
    }
    __syncthreads();
    if (tid < BM) {
        float tot = rbuf[tid * 2 + 0] + rbuf[tid * 2 + 1];
        parts[(size_t)blockIdx.y * rowStride + m0 + tid] = tot;
    }
}

// ---------------------------------------------------------------------------
// Calibration: n2 = sum of N-slice partials; n4 = n2^2; alpha/beta from max/min
// ---------------------------------------------------------------------------
__global__ void calib_kernel(const float* __restrict__ parts, int P, int nparts,
                             float* __restrict__ ab)
{
    __shared__ float smx[256], smn[256];
    const int tid = threadIdx.x;
    float mx = -1e30f, mn = 1e30f;
    for (int r = tid; r < P; r += 256) {
        float tot = 0.f;
        for (int y = 0; y < nparts; ++y) tot += parts[(size_t)y * P + r];
        float n4 = tot * tot;
        mx = fmaxf(mx, n4);
        mn = fminf(mn, n4);
    }
    smx[tid] = mx; smn[tid] = mn;
    __syncthreads();
    for (int s = 128; s > 0; s >>= 1) {
        if (tid < s) {
            smx[tid] = fmaxf(smx[tid], smx[tid + s]);
            smn[tid] = fminf(smn[tid], smn[tid + s]);
        }
        __syncthreads();
    }
    if (tid == 0) {
        float alpha = (1.0f - 0.001f) / (smx[0] - smn[0]);
        ab[0] = alpha;
        ab[1] = 0.001f - alpha * smn[0];
    }
}

// ---------------------------------------------------------------------------
// Finalize: warp per row; n2 from N-slice partials; out = (a*n2^2+b)*||xd||^2
// ---------------------------------------------------------------------------
__global__ __launch_bounds__(256)
void finalize_kernel(const float* __restrict__ x_dot,
                     const float* __restrict__ parts, int nparts,
                     const float* __restrict__ ab,
                     float* __restrict__ out, int B, int D)
{
    const int warp = (blockIdx.x * blockDim.x + threadIdx.x) >> 5;
    const int lane = threadIdx.x & 31;
    if (warp >= B) return;

    const int D4 = D >> 2;
    const float4* xd = reinterpret_cast<const float4*>(x_dot) + (size_t)warp * D4;
    float s = 0.f;
    for (int i = lane; i < D4; i += 32) {
        float4 v = xd[i];
        s += v.x * v.x + v.y * v.y + v.z * v.z + v.w * v.w;
    }
    #pragma unroll
    for (int off = 16; off > 0; off >>= 1)
        s += __shfl_down_sync(0xFFFFFFFFu, s, off);

    if (lane == 0) {
        float n2 = 0.f;
        for (int y = 0; y < nparts; ++y) n2 += parts[(size_t)y * B + warp];
        float a = ab[0], b = ab[1];
        out[warp] = (a * n2 * n2 + b) * s;
    }
}

// ---------------------------------------------------------------------------
// kernel_launch
// ---------------------------------------------------------------------------
extern "C" void kernel_launch(void* const* d_in, const int* in_sizes, int n_in,
                              void* d_out, int out_size)
{
    const float* x     = (const float*)d_in[0];
    const float* x_dot = (const float*)d_in[1];
    const float* pos   = (const float*)d_in[2];
    const float* W     = (const float*)d_in[3];
    float* out = (float*)d_out;

    const int D = (int)(sqrt((double)in_sizes[3]) + 0.5);
    const int B = in_sizes[0] / D;
    const int P = in_sizes[2] / D;
    const int NS = D / BN;   // 8 N-slices

    __half *xh, *ph, *wh;
    float *xparts, *pparts, *ab;
    cudaGetSymbolAddress((void**)&xh, g_xh);
    cudaGetSymbolAddress((void**)&ph, g_ph);
    cudaGetSymbolAddress((void**)&wh, g_wh);
    cudaGetSymbolAddress((void**)&xparts, g_xparts);
    cudaGetSymbolAddress((void**)&pparts, g_pparts);
    cudaGetSymbolAddress((void**)&ab, g_ab);

    cudaFuncSetAttribute(mma_gemm_norm,
                         cudaFuncAttributeMaxDynamicSharedMemorySize, SMEM_TOTAL);

    // prep: fp16 converts for rows, fp16 transpose for W
    {
        int n4 = (B * D) / 4;
        cvt_kernel<<<(n4 + 255) / 256, 256>>>(x, xh, n4);
        int p4 = (P * D) / 4;
        cvt_kernel<<<(p4 + 255) / 256, 256>>>(pos, ph, p4);
        wsplit_kernel<<<dim3(D / 32, D / 32), dim3(32, 8)>>>(W, wh, D);
    }

    // merged x + pos GEMM-norms (single launch)
    const int nxB = B / BM;
    const int npB = P / BM;
    mma_gemm_norm<<<dim3(nxB + npB, NS), 128, SMEM_TOTAL>>>(
        xh, ph, wh, D, nxB, xparts, B, pparts, P);

    // alpha/beta
    calib_kernel<<<1, 256>>>(pparts, P, NS, ab);

    // fused rowsum(x_dot^2) + scale
    const int rows_per_block = 256 / 32;
    finalize_kernel<<<(B + rows_per_block - 1) / rows_per_block, 256>>>(
        x_dot, xparts, NS, ab, out, B, D);
}

// round 8
// speedup vs baseline: 11.2500x; 1.0389x over previous
#include <cuda_runtime.h>
#include <cuda_fp16.h>
#include <math.h>
#include <stdint.h>

// ===========================================================================
// ScoreMagnitudeMetric via warp-level mma.sync fp16 single-term GEMM:
//   scores = x @ W  ~=  fp16(x) @ fp16(W^T)   (fp32 accumulation)
//   n2[b] = ||scores_b||^2 ; out[b] = (alpha*n2^2 + beta) * ||x_dot_b||^2
// R8: mbarrier producer/consumer pipeline (no per-chunk __syncthreads) so
// warps de-phase and LDSM/crossbar overlaps tensor; x_dot row-norms fused
// into the gemm launch as a third grid section.
// ===========================================================================

#define MAXB 32768
#define MAXP 2048
#define MAXD 1024

#define BM 128
#define BN 128
#define BK 64
#define NSLICE_MAX (MAXD / BN)   // 8

// scratch (device globals; no allocation allowed)
__device__ __half g_xh[(size_t)MAXB * MAXD];
__device__ __half g_ph[(size_t)MAXP * MAXD];
__device__ __half g_wh[(size_t)MAXD * MAXD];   // fp16(W^T)
__device__ float g_xparts[NSLICE_MAX * MAXB];
__device__ float g_pparts[NSLICE_MAX * MAXP];
__device__ float g_d2[MAXB];
__device__ float g_ab[2];

// ---------------------------------------------------------------------------
// helpers
// ---------------------------------------------------------------------------
__device__ __forceinline__ uint32_t smem_to_u32(const void* p) {
    uint32_t a;
    asm("{ .reg .u64 t; cvta.to.shared.u64 t, %1; cvt.u32.u64 %0, t; }"
        : "=r"(a) : "l"(p));
    return a;
}

#define CP_ASYNC16(sm, g) \
    asm volatile("cp.async.cg.shared.global [%0], [%1], 16;" :: "r"(sm), "l"(g) : "memory")

// deferred arrival on mbar when all prior cp.async of this thread complete
#define CP_MBAR_ARRIVE(mbar) \
    asm volatile("cp.async.mbarrier.arrive.noinc.shared.b64 [%0];" \
                 :: "r"((uint32_t)(mbar)) : "memory")

#define MBARRIER_INIT(addr, cnt) \
    asm volatile("mbarrier.init.shared.b64 [%0], %1;" \
                 :: "r"((uint32_t)(addr)), "r"((uint32_t)(cnt)) : "memory")

#define MBARRIER_ARRIVE(addr) \
    asm volatile("mbarrier.arrive.shared.b64 _, [%0];" \
                 :: "r"((uint32_t)(addr)) : "memory")

#define MBARRIER_WAIT_PARITY(addr, par) do {                                   \
    uint32_t _m = (uint32_t)(addr); uint32_t _p = (uint32_t)(par); uint32_t _d;\
    asm volatile("{\n\t.reg .pred p;\n\t"                                      \
        "mbarrier.try_wait.parity.acquire.cta.shared::cta.b64 p, [%1], %2;\n\t"\
        "selp.b32 %0, 1, 0, p;\n\t}" : "=r"(_d) : "r"(_m), "r"(_p) : "memory");\
    if (!_d) {                                                                 \
        asm volatile("{\n\t.reg .pred P1;\n\t"                                 \
            "WL_%=:\n\t"                                                       \
            "mbarrier.try_wait.parity.acquire.cta.shared::cta.b64 P1, [%0], %1, 0x989680;\n\t" \
            "@P1 bra.uni WD_%=;\n\t"                                           \
            "bra.uni WL_%=;\n\t"                                               \
            "WD_%=:\n\t}" :: "r"(_m), "r"(_p) : "memory");                     \
    }                                                                          \
} while (0)

__device__ __forceinline__ void ldsm_x4(uint32_t* r, uint32_t addr) {
    asm volatile("ldmatrix.sync.aligned.m8n8.x4.shared.b16 {%0,%1,%2,%3}, [%4];"
                 : "=r"(r[0]), "=r"(r[1]), "=r"(r[2]), "=r"(r[3]) : "r"(addr));
}

__device__ __forceinline__ void mma16816(float* c, const uint32_t* a,
                                         uint32_t b0, uint32_t b1) {
    asm volatile(
        "mma.sync.aligned.m16n8k16.row.col.f32.f16.f16.f32 "
        "{%0,%1,%2,%3}, {%4,%5,%6,%7}, {%8,%9}, {%0,%1,%2,%3};"
        : "+f"(c[0]), "+f"(c[1]), "+f"(c[2]), "+f"(c[3])
        : "r"(a[0]), "r"(a[1]), "r"(a[2]), "r"(a[3]), "r"(b0), "r"(b1));
}

// ---------------------------------------------------------------------------
// Prep: fp32 -> fp16 converts for x and pos in one launch
// ---------------------------------------------------------------------------
__global__ void cvt2_kernel(const float* __restrict__ x, __half* __restrict__ xh,
                            int nx4,
                            const float* __restrict__ p, __half* __restrict__ ph,
                            int np4)
{
    int i = blockIdx.x * blockDim.x + threadIdx.x;
    const float* src;
    __half* dst;
    if (i < nx4) { src = x; dst = xh; }
    else         { src = p; dst = ph; i -= nx4; if (i >= np4) return; }
    float4 v = reinterpret_cast<const float4*>(src)[i];
    __half2* hp = reinterpret_cast<__half2*>(dst) + 2 * i;
    hp[0] = __half2(__float2half_rn(v.x), __float2half_rn(v.y));
    hp[1] = __half2(__float2half_rn(v.z), __float2half_rn(v.w));
}

// W [k][j] -> Wt [j][k] fp16 (32x32 smem transpose tiles)
__global__ void wsplit_kernel(const float* __restrict__ W,
                              __half* __restrict__ wth, int D)
{
    __shared__ float t[32][33];
    const int j0 = blockIdx.x * 32, k0 = blockIdx.y * 32;
    const int tx = threadIdx.x, ty = threadIdx.y;  // (32, 8)
    #pragma unroll
    for (int r = 0; r < 4; ++r)
        t[ty + 8 * r][tx] = W[(size_t)(k0 + ty + 8 * r) * D + j0 + tx];
    __syncthreads();
    #pragma unroll
    for (int r = 0; r < 4; ++r) {
        float v = t[tx][ty + 8 * r];
        wth[(size_t)(j0 + ty + 8 * r) * D + k0 + tx] = __float2half_rn(v);
    }
}

// ---------------------------------------------------------------------------
// mma.sync GEMM-norm + fused x_dot row-norms. Grid sections on blockIdx.x:
//   [0, nxB)            : rows of X  -> xparts
//   [nxB, nxB+npB)      : rows of Pm -> pparts
//   [nxB+npB, +ndB)     : x_dot row sum-of-squares -> d2   (y==0 only)
// GEMM block: 128x128, 4 warps (2x2 of 64x64), K in 64-chunks, 3-stage
// cp.async pipeline driven by mbarriers (full/consumed per stage) -- NO
// per-chunk __syncthreads, so warps drift and LDSM overlaps MMA.
// Smem tile rows: 64 halves = 128 B data, 144 B stride (conflict-free ldsm).
// ---------------------------------------------------------------------------
#define TILE_B   18432              // 128 rows * 144 B
#define A_OFF    0
#define B_OFF    (TILE_B)
#define STAGE_B  (2 * TILE_B)       // 36864
#define NSTAGE   3
#define MBAR_OFF (NSTAGE * STAGE_B)         // 110592
#define SMEM_TOTAL (MBAR_OFF + 64)          // 110656

__global__ __launch_bounds__(128, 2)
void mma_gemm_norm(const __half* __restrict__ X,
                   const __half* __restrict__ Pm,
                   const __half* __restrict__ Wm,
                   const float* __restrict__ x_dot,
                   int D, int nxB, int npB,
                   float* __restrict__ xparts, int Brows,
                   float* __restrict__ pparts, int Prows,
                   float* __restrict__ d2)
{
    extern __shared__ __align__(128) char smem[];
    const uint32_t sm0 = smem_to_u32(smem);

    const int tid  = threadIdx.x;
    const int wid  = tid >> 5;
    const int lane = tid & 31;

    // ---- section 3: x_dot row-norms (DRAM-bound filler blocks) ----------
    if ((int)blockIdx.x >= nxB + npB) {
        if (blockIdx.y != 0) return;
        const int base = ((int)blockIdx.x - nxB - npB) * 128 + wid * 32;
        const int D4 = D >> 2;
        for (int r = 0; r < 32; ++r) {
            const float4* xd = reinterpret_cast<const float4*>(x_dot)
                             + (size_t)(base + r) * D4;
            float s = 0.f;
            for (int i = lane; i < D4; i += 32) {
                float4 v = xd[i];
                s += v.x * v.x + v.y * v.y + v.z * v.z + v.w * v.w;
            }
            #pragma unroll
            for (int off = 16; off > 0; off >>= 1)
                s += __shfl_down_sync(0xFFFFFFFFu, s, off);
            if (lane == 0) d2[base + r] = s;
        }
        return;
    }

    // ---- sections 1+2: GEMM-norm ----------------------------------------
    const int wm   = wid >> 1;          // 0..1 -> rows wm*64
    const int wn   = wid & 1;           // 0..1 -> cols wn*64
    const int KC   = D / BK;            // 16

    const bool isX = ((int)blockIdx.x < nxB);
    const int  mb  = isX ? (int)blockIdx.x : (int)blockIdx.x - nxB;
    const int  m0  = mb * BM;
    const int  n0  = blockIdx.y * BN;
    float* parts   = isX ? xparts : pparts;
    const int rowStride = isX ? Brows : Prows;

    const __half* gA = (isX ? X : Pm) + (size_t)m0 * D;
    const __half* gB = Wm + (size_t)n0 * D;

    const uint32_t FULL = sm0 + MBAR_OFF;        // 3 x 8B
    const uint32_t CONS = sm0 + MBAR_OFF + 24;   // 3 x 8B

    if (tid == 0) {
        #pragma unroll
        for (int s = 0; s < NSTAGE; ++s) {
            MBARRIER_INIT(FULL + 8 * s, 128);
            MBARRIER_INIT(CONS + 8 * s, 128);
        }
    }
    __syncthreads();

    float acc[4][8][4];
    #pragma unroll
    for (int i = 0; i < 4; ++i)
        #pragma unroll
        for (int j = 0; j < 8; ++j)
            #pragma unroll
            for (int c = 0; c < 4; ++c) acc[i][j][c] = 0.f;

    auto load_chunk = [&](int kc, int s) {
        const uint32_t sb = sm0 + (uint32_t)s * STAGE_B;
        const int kb = kc * BK;          // halves
        #pragma unroll
        for (int i = 0; i < 8; ++i) {
            int idx = tid + 128 * i;     // 0..1023
            int r = idx >> 3, c = idx & 7;
            uint32_t so = (uint32_t)(r * 144 + c * 16);
            size_t go = (size_t)r * D + kb + c * 8;
            CP_ASYNC16(sb + A_OFF + so, gA + go);
            CP_ASYNC16(sb + B_OFF + so, gB + go);
        }
    };

    // ldmatrix per-lane address pieces (within-warp), hoisted
    const int a_row = (lane & 15);
    const int a_ku  = (lane >> 4);
    const int b_row = ((lane >> 4) << 3) + (lane & 7);
    const int b_ku  = ((lane >> 3) & 1);
    const int mrow  = wm * 64;
    const int nrow  = wn * 64;
    const uint32_t aBase0 = (uint32_t)((mrow + a_row) * 144 + a_ku * 16);
    const uint32_t bBase0 = (uint32_t)((nrow + b_row) * 144 + b_ku * 16);

    // prologue: chunks 0 and 1 in flight (deferred arrivals on FULL)
    load_chunk(0, 0);
    CP_MBAR_ARRIVE(FULL + 0);
    load_chunk(1, 1);
    CP_MBAR_ARRIVE(FULL + 8);

    for (int kc = 0; kc < KC; ++kc) {
        const int s = kc % NSTAGE;

        // produce chunk kc+2 into stage (kc+2)%3 (wait its previous reader)
        if (kc + 2 < KC) {
            const int s2 = (kc + 2) % NSTAGE;
            const uint32_t pc = (kc == 0) ? 1u : (uint32_t)(((kc - 1) / 3) & 1);
            MBARRIER_WAIT_PARITY(CONS + 8 * s2, pc);
            load_chunk(kc + 2, s2);
            CP_MBAR_ARRIVE(FULL + 8 * s2);
        }

        // consume chunk kc
        MBARRIER_WAIT_PARITY(FULL + 8 * s, (uint32_t)((kc / 3) & 1));

        const uint32_t sb = sm0 + (uint32_t)s * STAGE_B;
        const uint32_t aB = sb + A_OFF + aBase0;
        const uint32_t bB = sb + B_OFF + bBase0;
        #pragma unroll
        for (int ks = 0; ks < 4; ++ks) {        // four k16 steps per chunk
            const uint32_t kOff = (uint32_t)(ks * 32);
            uint32_t ah[4][4], bh[4][4];
            #pragma unroll
            for (int mt = 0; mt < 4; ++mt)
                ldsm_x4(ah[mt], aB + kOff + (uint32_t)(mt * 16 * 144));
            #pragma unroll
            for (int ng = 0; ng < 4; ++ng)
                ldsm_x4(bh[ng], bB + kOff + (uint32_t)(ng * 16 * 144));
            #pragma unroll
            for (int mt = 0; mt < 4; ++mt) {
                #pragma unroll
                for (int nt = 0; nt < 8; ++nt) {
                    uint32_t b0 = bh[nt >> 1][2 * (nt & 1)];
                    uint32_t b1 = bh[nt >> 1][2 * (nt & 1) + 1];
                    mma16816(acc[mt][nt], ah[mt], b0, b1);
                }
            }
        }

        // this thread is done reading stage s
        MBARRIER_ARRIVE(CONS + 8 * s);
    }
    __syncthreads();   // all warps done (and all loads consumed) before reuse

    // ---- epilogue: row-wise sum of squares -------------------------------
    float* rbuf = reinterpret_cast<float*>(smem);   // [128][2]
    float rs0[4], rs1[4];
    #pragma unroll
    for (int mt = 0; mt < 4; ++mt) {
        float s0 = 0.f, s1 = 0.f;
        #pragma unroll
        for (int nt = 0; nt < 8; ++nt) {
            s0 += acc[mt][nt][0] * acc[mt][nt][0] + acc[mt][nt][1] * acc[mt][nt][1];
            s1 += acc[mt][nt][2] * acc[mt][nt][2] + acc[mt][nt][3] * acc[mt][nt][3];
        }
        s0 += __shfl_xor_sync(0xFFFFFFFFu, s0, 1);
        s0 += __shfl_xor_sync(0xFFFFFFFFu, s0, 2);
        s1 += __shfl_xor_sync(0xFFFFFFFFu, s1, 1);
        s1 += __shfl_xor_sync(0xFFFFFFFFu, s1, 2);
        rs0[mt] = s0;
        rs1[mt] = s1;
    }
    if ((lane & 3) == 0) {
        int rq = lane >> 2;
        #pragma unroll
        for (int mt = 0; mt < 4; ++mt) {
            int row = mrow + mt * 16 + rq;
            rbuf[row * 2 + wn] = rs0[mt];
            rbuf[(row + 8) * 2 + wn] = rs1[mt];
        }
    }
    __syncthreads();
    if (tid < BM) {
        float tot = rbuf[tid * 2 + 0] + rbuf[tid * 2 + 1];
        parts[(size_t)blockIdx.y * rowStride + m0 + tid] = tot;
    }
}

// ---------------------------------------------------------------------------
// Calibration: n2 = sum of N-slice partials; n4 = n2^2; alpha/beta from max/min
// ---------------------------------------------------------------------------
__global__ void calib_kernel(const float* __restrict__ parts, int P, int nparts,
                             float* __restrict__ ab)
{
    __shared__ float smx[256], smn[256];
    const int tid = threadIdx.x;
    float mx = -1e30f, mn = 1e30f;
    for (int r = tid; r < P; r += 256) {
        float tot = 0.f;
        for (int y = 0; y < nparts; ++y) tot += parts[(size_t)y * P + r];
        float n4 = tot * tot;
        mx = fmaxf(mx, n4);
        mn = fminf(mn, n4);
    }
    smx[tid] = mx; smn[tid] = mn;
    __syncthreads();
    for (int s = 128; s > 0; s >>= 1) {
        if (tid < s) {
            smx[tid] = fmaxf(smx[tid], smx[tid + s]);
            smn[tid] = fminf(smn[tid], smn[tid + s]);
        }
        __syncthreads();
    }
    if (tid == 0) {
        float alpha = (1.0f - 0.001f) / (smx[0] - smn[0]);
        ab[0] = alpha;
        ab[1] = 0.001f - alpha * smn[0];
    }
}

// ---------------------------------------------------------------------------
// Combine: out[b] = (a*n2^2 + b) * d2[b]    (tiny; ~1.3MB of reads)
// ---------------------------------------------------------------------------
__global__ __launch_bounds__(256)
void combine_kernel(const float* __restrict__ parts, int nparts,
                    const float* __restrict__ d2,
                    const float* __restrict__ ab,
                    float* __restrict__ out, int B)
{
    const int b = blockIdx.x * blockDim.x + threadIdx.x;
    if (b >= B) return;
    float n2 = 0.f;
    for (int y = 0; y < nparts; ++y) n2 += parts[(size_t)y * B + b];
    out[b] = (ab[0] * n2 * n2 + ab[1]) * d2[b];
}

// ---------------------------------------------------------------------------
// kernel_launch
// ---------------------------------------------------------------------------
extern "C" void kernel_launch(void* const* d_in, const int* in_sizes, int n_in,
                              void* d_out, int out_size)
{
    const float* x     = (const float*)d_in[0];
    const float* x_dot = (const float*)d_in[1];
    const float* pos   = (const float*)d_in[2];
    const float* W     = (const float*)d_in[3];
    float* out = (float*)d_out;

    const int D = (int)(sqrt((double)in_sizes[3]) + 0.5);
    const int B = in_sizes[0] / D;
    const int P = in_sizes[2] / D;
    const int NS = D / BN;   // 8 N-slices

    __half *xh, *ph, *wh;
    float *xparts, *pparts, *d2, *ab;
    cudaGetSymbolAddress((void**)&xh, g_xh);
    cudaGetSymbolAddress((void**)&ph, g_ph);
    cudaGetSymbolAddress((void**)&wh, g_wh);
    cudaGetSymbolAddress((void**)&xparts, g_xparts);
    cudaGetSymbolAddress((void**)&pparts, g_pparts);
    cudaGetSymbolAddress((void**)&d2, g_d2);
    cudaGetSymbolAddress((void**)&ab, g_ab);

    cudaFuncSetAttribute(mma_gemm_norm,
                         cudaFuncAttributeMaxDynamicSharedMemorySize, SMEM_TOTAL);

    // prep: fp16 converts (one launch) + W transpose
    const int nx4 = (B * D) / 4;
    const int np4 = (P * D) / 4;
    cvt2_kernel<<<(nx4 + np4 + 255) / 256, 256>>>(x, xh, nx4, pos, ph, np4);
    wsplit_kernel<<<dim3(D / 32, D / 32), dim3(32, 8)>>>(W, wh, D);

    // merged x-gemm + pos-gemm + x_dot row-norms (single launch)
    const int nxB = B / BM;
    const int npB = P / BM;
    const int ndB = B / 128;
    mma_gemm_norm<<<dim3(nxB + npB + ndB, NS), 128, SMEM_TOTAL>>>(
        xh, ph, wh, x_dot, D, nxB, npB, xparts, B, pparts, P, d2);

    // alpha/beta
    calib_kernel<<<1, 256>>>(pparts, P, NS, ab);

    // out = (a*n2^2+b) * d2
    combine_kernel<<<(B + 255) / 256, 256>>>(xparts, NS, d2, ab, out, B);
}

// round 10
// speedup vs baseline: 11.3711x; 1.0108x over previous
#include <cuda_runtime.h>
#include <cuda_fp16.h>
#include <math.h>
#include <stdint.h>

// ===========================================================================
// ScoreMagnitudeMetric via warp-level mma.sync fp16 single-term GEMM:
//   scores = x @ W  ~=  fp16(x) @ fp16(W^T)   (fp32 accumulation)
//   n2[b] = ||scores_b||^2 ; out[b] = (alpha*n2^2 + beta) * ||x_dot_b||^2
// R9 resubmit (R9 bench was an infra failure — container died, kernel never
// ran): per-warp elected mbarrier arrivals (8x less ATOMS on consumed-bars);
// calibration fused into combine (kills a 10us serial single-block launch).
// ===========================================================================

#define MAXB 32768
#define MAXP 2048
#define MAXD 1024

#define BM 128
#define BN 128
#define BK 64
#define NSLICE_MAX (MAXD / BN)   // 8

// scratch (device globals; no allocation allowed)
__device__ __half g_xh[(size_t)MAXB * MAXD];
__device__ __half g_ph[(size_t)MAXP * MAXD];
__device__ __half g_wh[(size_t)MAXD * MAXD];   // fp16(W^T)
__device__ float g_xparts[NSLICE_MAX * MAXB];
__device__ float g_pparts[NSLICE_MAX * MAXP];
__device__ float g_d2[MAXB];

// ---------------------------------------------------------------------------
// helpers
// ---------------------------------------------------------------------------
__device__ __forceinline__ uint32_t smem_to_u32(const void* p) {
    uint32_t a;
    asm("{ .reg .u64 t; cvta.to.shared.u64 t, %1; cvt.u32.u64 %0, t; }"
        : "=r"(a) : "l"(p));
    return a;
}

#define CP_ASYNC16(sm, g) \
    asm volatile("cp.async.cg.shared.global [%0], [%1], 16;" :: "r"(sm), "l"(g) : "memory")

// deferred arrival on mbar when all prior cp.async of this thread complete
#define CP_MBAR_ARRIVE(mbar) \
    asm volatile("cp.async.mbarrier.arrive.noinc.shared.b64 [%0];" \
                 :: "r"((uint32_t)(mbar)) : "memory")

#define MBARRIER_INIT(addr, cnt) \
    asm volatile("mbarrier.init.shared.b64 [%0], %1;" \
                 :: "r"((uint32_t)(addr)), "r"((uint32_t)(cnt)) : "memory")

#define MBARRIER_ARRIVE(addr) \
    asm volatile("mbarrier.arrive.shared.b64 _, [%0];" \
                 :: "r"((uint32_t)(addr)) : "memory")

#define MBARRIER_WAIT_PARITY(addr, par) do {                                   \
    uint32_t _m = (uint32_t)(addr); uint32_t _p = (uint32_t)(par); uint32_t _d;\
    asm volatile("{\n\t.reg .pred p;\n\t"                                      \
        "mbarrier.try_wait.parity.acquire.cta.shared::cta.b64 p, [%1], %2;\n\t"\
        "selp.b32 %0, 1, 0, p;\n\t}" : "=r"(_d) : "r"(_m), "r"(_p) : "memory");\
    if (!_d) {                                                                 \
        asm volatile("{\n\t.reg .pred P1;\n\t"                                 \
            "WL_%=:\n\t"                                                       \
            "mbarrier.try_wait.parity.acquire.cta.shared::cta.b64 P1, [%0], %1, 0x989680;\n\t" \
            "@P1 bra.uni WD_%=;\n\t"                                           \
            "bra.uni WL_%=;\n\t"                                               \
            "WD_%=:\n\t}" :: "r"(_m), "r"(_p) : "memory");                     \
    }                                                                          \
} while (0)

__device__ __forceinline__ void ldsm_x4(uint32_t* r, uint32_t addr) {
    asm volatile("ldmatrix.sync.aligned.m8n8.x4.shared.b16 {%0,%1,%2,%3}, [%4];"
                 : "=r"(r[0]), "=r"(r[1]), "=r"(r[2]), "=r"(r[3]) : "r"(addr));
}

__device__ __forceinline__ void mma16816(float* c, const uint32_t* a,
                                         uint32_t b0, uint32_t b1) {
    asm volatile(
        "mma.sync.aligned.m16n8k16.row.col.f32.f16.f16.f32 "
        "{%0,%1,%2,%3}, {%4,%5,%6,%7}, {%8,%9}, {%0,%1,%2,%3};"
        : "+f"(c[0]), "+f"(c[1]), "+f"(c[2]), "+f"(c[3])
        : "r"(a[0]), "r"(a[1]), "r"(a[2]), "r"(a[3]), "r"(b0), "r"(b1));
}

// ---------------------------------------------------------------------------
// Prep: fp32 -> fp16 converts for x and pos in one launch
// ---------------------------------------------------------------------------
__global__ void cvt2_kernel(const float* __restrict__ x, __half* __restrict__ xh,
                            int nx4,
                            const float* __restrict__ p, __half* __restrict__ ph,
                            int np4)
{
    int i = blockIdx.x * blockDim.x + threadIdx.x;
    const float* src;
    __half* dst;
    if (i < nx4) { src = x; dst = xh; }
    else         { src = p; dst = ph; i -= nx4; if (i >= np4) return; }
    float4 v = reinterpret_cast<const float4*>(src)[i];
    __half2* hp = reinterpret_cast<__half2*>(dst) + 2 * i;
    hp[0] = __half2(__float2half_rn(v.x), __float2half_rn(v.y));
    hp[1] = __half2(__float2half_rn(v.z), __float2half_rn(v.w));
}

// W [k][j] -> Wt [j][k] fp16 (32x32 smem transpose tiles)
__global__ void wsplit_kernel(const float* __restrict__ W,
                              __half* __restrict__ wth, int D)
{
    __shared__ float t[32][33];
    const int j0 = blockIdx.x * 32, k0 = blockIdx.y * 32;
    const int tx = threadIdx.x, ty = threadIdx.y;  // (32, 8)
    #pragma unroll
    for (int r = 0; r < 4; ++r)
        t[ty + 8 * r][tx] = W[(size_t)(k0 + ty + 8 * r) * D + j0 + tx];
    __syncthreads();
    #pragma unroll
    for (int r = 0; r < 4; ++r) {
        float v = t[tx][ty + 8 * r];
        wth[(size_t)(j0 + ty + 8 * r) * D + k0 + tx] = __float2half_rn(v);
    }
}

// ---------------------------------------------------------------------------
// mma.sync GEMM-norm + fused x_dot row-norms. Grid sections on blockIdx.x:
//   [0, nxB)            : rows of X  -> xparts
//   [nxB, nxB+npB)      : rows of Pm -> pparts
//   [nxB+npB, +ndB)     : x_dot row sum-of-squares -> d2   (y==0 only)
// GEMM block: 128x128, 4 warps (2x2 of 64x64), K in 64-chunks, 3-stage
// cp.async pipeline driven by mbarriers: FULL[s] (128 cp.async arrivals),
// CONS[s] (4 per-warp elected arrivals).
// Smem tile rows: 64 halves = 128 B data, 144 B stride (conflict-free ldsm).
// ---------------------------------------------------------------------------
#define TILE_B   18432              // 128 rows * 144 B
#define A_OFF    0
#define B_OFF    (TILE_B)
#define STAGE_B  (2 * TILE_B)       // 36864
#define NSTAGE   3
#define MBAR_OFF (NSTAGE * STAGE_B)         // 110592
#define SMEM_TOTAL (MBAR_OFF + 64)          // 110656

__global__ __launch_bounds__(128, 2)
void mma_gemm_norm(const __half* __restrict__ X,
                   const __half* __restrict__ Pm,
                   const __half* __restrict__ Wm,
                   const float* __restrict__ x_dot,
                   int D, int nxB, int npB,
                   float* __restrict__ xparts, int Brows,
                   float* __restrict__ pparts, int Prows,
                   float* __restrict__ d2)
{
    extern __shared__ __align__(128) char smem[];
    const uint32_t sm0 = smem_to_u32(smem);

    const int tid  = threadIdx.x;
    const int wid  = tid >> 5;
    const int lane = tid & 31;

    // ---- section 3: x_dot row-norms (DRAM-bound filler blocks) ----------
    if ((int)blockIdx.x >= nxB + npB) {
        if (blockIdx.y != 0) return;
        const int base = ((int)blockIdx.x - nxB - npB) * 128 + wid * 32;
        const int D4 = D >> 2;
        for (int r = 0; r < 32; ++r) {
            const float4* xd = reinterpret_cast<const float4*>(x_dot)
                             + (size_t)(base + r) * D4;
            float s = 0.f;
            for (int i = lane; i < D4; i += 32) {
                float4 v = xd[i];
                s += v.x * v.x + v.y * v.y + v.z * v.z + v.w * v.w;
            }
            #pragma unroll
            for (int off = 16; off > 0; off >>= 1)
                s += __shfl_down_sync(0xFFFFFFFFu, s, off);
            if (lane == 0) d2[base + r] = s;
        }
        return;
    }

    // ---- sections 1+2: GEMM-norm ----------------------------------------
    const int wm   = wid >> 1;          // 0..1 -> rows wm*64
    const int wn   = wid & 1;           // 0..1 -> cols wn*64
    const int KC   = D / BK;            // 16

    const bool isX = ((int)blockIdx.x < nxB);
    const int  mb  = isX ? (int)blockIdx.x : (int)blockIdx.x - nxB;
    const int  m0  = mb * BM;
    const int  n0  = blockIdx.y * BN;
    float* parts   = isX ? xparts : pparts;
    const int rowStride = isX ? Brows : Prows;

    const __half* gA = (isX ? X : Pm) + (size_t)m0 * D;
    const __half* gB = Wm + (size_t)n0 * D;

    const uint32_t FULL = sm0 + MBAR_OFF;        // 3 x 8B
    const uint32_t CONS = sm0 + MBAR_OFF + 24;   // 3 x 8B

    if (tid == 0) {
        #pragma unroll
        for (int s = 0; s < NSTAGE; ++s) {
            MBARRIER_INIT(FULL + 8 * s, 128);   // all threads' cp.async groups
            MBARRIER_INIT(CONS + 8 * s, 4);     // one elected lane per warp
        }
    }
    __syncthreads();

    float acc[4][8][4];
    #pragma unroll
    for (int i = 0; i < 4; ++i)
        #pragma unroll
        for (int j = 0; j < 8; ++j)
            #pragma unroll
            for (int c = 0; c < 4; ++c) acc[i][j][c] = 0.f;

    auto load_chunk = [&](int kc, int s) {
        const uint32_t sb = sm0 + (uint32_t)s * STAGE_B;
        const int kb = kc * BK;          // halves
        #pragma unroll
        for (int i = 0; i < 8; ++i) {
            int idx = tid + 128 * i;     // 0..1023
            int r = idx >> 3, c = idx & 7;
            uint32_t so = (uint32_t)(r * 144 + c * 16);
            size_t go = (size_t)r * D + kb + c * 8;
            CP_ASYNC16(sb + A_OFF + so, gA + go);
            CP_ASYNC16(sb + B_OFF + so, gB + go);
        }
    };

    // ldmatrix per-lane address pieces (within-warp), hoisted
    const int a_row = (lane & 15);
    const int a_ku  = (lane >> 4);
    const int b_row = ((lane >> 4) << 3) + (lane & 7);
    const int b_ku  = ((lane >> 3) & 1);
    const int mrow  = wm * 64;
    const int nrow  = wn * 64;
    const uint32_t aBase0 = (uint32_t)((mrow + a_row) * 144 + a_ku * 16);
    const uint32_t bBase0 = (uint32_t)((nrow + b_row) * 144 + b_ku * 16);

    // prologue: chunks 0 and 1 in flight (deferred arrivals on FULL)
    load_chunk(0, 0);
    CP_MBAR_ARRIVE(FULL + 0);
    load_chunk(1, 1);
    CP_MBAR_ARRIVE(FULL + 8);

    for (int kc = 0; kc < KC; ++kc) {
        const int s = kc % NSTAGE;

        // produce chunk kc+2 into stage (kc+2)%3 (wait its previous reader)
        if (kc + 2 < KC) {
            const int s2 = (kc + 2) % NSTAGE;
            const uint32_t pc = (kc == 0) ? 1u : (uint32_t)(((kc - 1) / 3) & 1);
            MBARRIER_WAIT_PARITY(CONS + 8 * s2, pc);
            load_chunk(kc + 2, s2);
            CP_MBAR_ARRIVE(FULL + 8 * s2);
        }

        // consume chunk kc
        MBARRIER_WAIT_PARITY(FULL + 8 * s, (uint32_t)((kc / 3) & 1));

        const uint32_t sb = sm0 + (uint32_t)s * STAGE_B;
        const uint32_t aB = sb + A_OFF + aBase0;
        const uint32_t bB = sb + B_OFF + bBase0;
        #pragma unroll
        for (int ks = 0; ks < 4; ++ks) {        // four k16 steps per chunk
            const uint32_t kOff = (uint32_t)(ks * 32);
            uint32_t ah[4][4], bh[4][4];
            #pragma unroll
            for (int mt = 0; mt < 4; ++mt)
                ldsm_x4(ah[mt], aB + kOff + (uint32_t)(mt * 16 * 144));
            #pragma unroll
            for (int ng = 0; ng < 4; ++ng)
                ldsm_x4(bh[ng], bB + kOff + (uint32_t)(ng * 16 * 144));
            #pragma unroll
            for (int mt = 0; mt < 4; ++mt) {
                #pragma unroll
                for (int nt = 0; nt < 8; ++nt) {
                    uint32_t b0 = bh[nt >> 1][2 * (nt & 1)];
                    uint32_t b1 = bh[nt >> 1][2 * (nt & 1) + 1];
                    mma16816(acc[mt][nt], ah[mt], b0, b1);
                }
            }
        }

        // warp done reading stage s: one elected arrival per warp.
        // (warp is converged here; ldsm results all consumed)
        if (lane == 0) MBARRIER_ARRIVE(CONS + 8 * s);
    }
    __syncthreads();   // all warps done (and all loads consumed) before reuse

    // ---- epilogue: row-wise sum of squares -------------------------------
    float* rbuf = reinterpret_cast<float*>(smem);   // [128][2]
    float rs0[4], rs1[4];
    #pragma unroll
    for (int mt = 0; mt < 4; ++mt) {
        float s0 = 0.f, s1 = 0.f;
        #pragma unroll
        for (int nt = 0; nt < 8; ++nt) {
            s0 += acc[mt][nt][0] * acc[mt][nt][0] + acc[mt][nt][1] * acc[mt][nt][1];
            s1 += acc[mt][nt][2] * acc[mt][nt][2] + acc[mt][nt][3] * acc[mt][nt][3];
        }
        s0 += __shfl_xor_sync(0xFFFFFFFFu, s0, 1);
        s0 += __shfl_xor_sync(0xFFFFFFFFu, s0, 2);
        s1 += __shfl_xor_sync(0xFFFFFFFFu, s1, 1);
        s1 += __shfl_xor_sync(0xFFFFFFFFu, s1, 2);
        rs0[mt] = s0;
        rs1[mt] = s1;
    }
    if ((lane & 3) == 0) {
        int rq = lane >> 2;
        #pragma unroll
        for (int mt = 0; mt < 4; ++mt) {
            int row = mrow + mt * 16 + rq;
            rbuf[row * 2 + wn] = rs0[mt];
            rbuf[(row + 8) * 2 + wn] = rs1[mt];
        }
    }
    __syncthreads();
    if (tid < BM) {
        float tot = rbuf[tid * 2 + 0] + rbuf[tid * 2 + 1];
        parts[(size_t)blockIdx.y * rowStride + m0 + tid] = tot;
    }
}

// ---------------------------------------------------------------------------
// Combine (calibration fused): every block redundantly computes alpha/beta
// from pparts (identical deterministic reduction -> identical results), then
// out[b] = (alpha*n2^2 + beta) * d2[b].
// ---------------------------------------------------------------------------
__global__ __launch_bounds__(256)
void combine_kernel(const float* __restrict__ xparts, int nparts,
                    const float* __restrict__ pparts, int P,
                    const float* __restrict__ d2,
                    float* __restrict__ out, int B)
{
    __shared__ float smx[256], smn[256];
    const int tid = threadIdx.x;

    // calibration (same in every block; deterministic)
    float mx = -1e30f, mn = 1e30f;
    for (int r = tid; r < P; r += 256) {
        float tot = 0.f;
        for (int y = 0; y < nparts; ++y) tot += pparts[(size_t)y * P + r];
        float n4 = tot * tot;
        mx = fmaxf(mx, n4);
        mn = fminf(mn, n4);
    }
    smx[tid] = mx; smn[tid] = mn;
    __syncthreads();
    for (int s = 128; s > 0; s >>= 1) {
        if (tid < s) {
            smx[tid] = fmaxf(smx[tid], smx[tid + s]);
            smn[tid] = fminf(smn[tid], smn[tid + s]);
        }
        __syncthreads();
    }
    const float alpha = (1.0f - 0.001f) / (smx[0] - smn[0]);
    const float beta  = 0.001f - alpha * smn[0];

    const int b = blockIdx.x * blockDim.x + tid;
    if (b >= B) return;
    float n2 = 0.f;
    for (int y = 0; y < nparts; ++y) n2 += xparts[(size_t)y * B + b];
    out[b] = (alpha * n2 * n2 + beta) * d2[b];
}

// ---------------------------------------------------------------------------
// kernel_launch
// ---------------------------------------------------------------------------
extern "C" void kernel_launch(void* const* d_in, const int* in_sizes, int n_in,
                              void* d_out, int out_size)
{
    const float* x     = (const float*)d_in[0];
    const float* x_dot = (const float*)d_in[1];
    const float* pos   = (const float*)d_in[2];
    const float* W     = (const float*)d_in[3];
    float* out = (float*)d_out;

    const int D = (int)(sqrt((double)in_sizes[3]) + 0.5);
    const int B = in_sizes[0] / D;
    const int P = in_sizes[2] / D;
    const int NS = D / BN;   // 8 N-slices

    __half *xh, *ph, *wh;
    float *xparts, *pparts, *d2;
    cudaGetSymbolAddress((void**)&xh, g_xh);
    cudaGetSymbolAddress((void**)&ph, g_ph);
    cudaGetSymbolAddress((void**)&wh, g_wh);
    cudaGetSymbolAddress((void**)&xparts, g_xparts);
    cudaGetSymbolAddress((void**)&pparts, g_pparts);
    cudaGetSymbolAddress((void**)&d2, g_d2);

    cudaFuncSetAttribute(mma_gemm_norm,
                         cudaFuncAttributeMaxDynamicSharedMemorySize, SMEM_TOTAL);

    // prep: fp16 converts (one launch) + W transpose
    const int nx4 = (B * D) / 4;
    const int np4 = (P * D) / 4;
    wsplit_kernel<<<dim3(D / 32, D / 32), dim3(32, 8)>>>(W, wh, D);
    cvt2_kernel<<<(nx4 + np4 + 255) / 256, 256>>>(x, xh, nx4, pos, ph, np4);

    // merged x-gemm + pos-gemm + x_dot row-norms (single launch)
    const int nxB = B / BM;
    const int npB = P / BM;
    const int ndB = B / 128;
    mma_gemm_norm<<<dim3(nxB + npB + ndB, NS), 128, SMEM_TOTAL>>>(
        xh, ph, wh, x_dot, D, nxB, npB, xparts, B, pparts, P, d2);

    // fused calibration + combine
    combine_kernel<<<(B + 255) / 256, 256>>>(xparts, NS, pparts, P, d2, out, B);
}

// round 11
// speedup vs baseline: 11.5005x; 1.0114x over previous
#include <cuda_runtime.h>
#include <cuda_fp16.h>
#include <math.h>
#include <stdint.h>

// ===========================================================================
// ScoreMagnitudeMetric via warp-level mma.sync fp16 single-term GEMM:
//   scores = x @ W  ~=  fp16(x) @ fp16(W^T)   (fp32 accumulation)
//   n2[b] = ||scores_b||^2 ; out[b] = (alpha*n2^2 + beta) * ||x_dot_b||^2
// R11: prep merged into one launch (W-transpose + converts + atomic-cell
// init); calibration via per-block atomicMax/Min on int-punned positive
// floats (deterministic); combine reads 2 scalars instead of re-reducing.
// ===========================================================================

#define MAXB 32768
#define MAXP 2048
#define MAXD 1024

#define BM 128
#define BN 128
#define BK 64
#define NSLICE_MAX (MAXD / BN)   // 8

// scratch (device globals; no allocation allowed)
__device__ __half g_xh[(size_t)MAXB * MAXD];
__device__ __half g_ph[(size_t)MAXP * MAXD];
__device__ __half g_wh[(size_t)MAXD * MAXD];   // fp16(W^T)
__device__ float g_xparts[NSLICE_MAX * MAXB];
__device__ float g_pparts[NSLICE_MAX * MAXP];
__device__ float g_d2[MAXB];
__device__ int   g_cal[2];                     // [0]=max(n4) bits, [1]=min(n4) bits

// ---------------------------------------------------------------------------
// helpers
// ---------------------------------------------------------------------------
__device__ __forceinline__ uint32_t smem_to_u32(const void* p) {
    uint32_t a;
    asm("{ .reg .u64 t; cvta.to.shared.u64 t, %1; cvt.u32.u64 %0, t; }"
        : "=r"(a) : "l"(p));
    return a;
}

#define CP_ASYNC16(sm, g) \
    asm volatile("cp.async.cg.shared.global [%0], [%1], 16;" :: "r"(sm), "l"(g) : "memory")

// deferred arrival on mbar when all prior cp.async of this thread complete
#define CP_MBAR_ARRIVE(mbar) \
    asm volatile("cp.async.mbarrier.arrive.noinc.shared.b64 [%0];" \
                 :: "r"((uint32_t)(mbar)) : "memory")

#define MBARRIER_INIT(addr, cnt) \
    asm volatile("mbarrier.init.shared.b64 [%0], %1;" \
                 :: "r"((uint32_t)(addr)), "r"((uint32_t)(cnt)) : "memory")

#define MBARRIER_ARRIVE(addr) \
    asm volatile("mbarrier.arrive.shared.b64 _, [%0];" \
                 :: "r"((uint32_t)(addr)) : "memory")

#define MBARRIER_WAIT_PARITY(addr, par) do {                                   \
    uint32_t _m = (uint32_t)(addr); uint32_t _p = (uint32_t)(par); uint32_t _d;\
    asm volatile("{\n\t.reg .pred p;\n\t"                                      \
        "mbarrier.try_wait.parity.acquire.cta.shared::cta.b64 p, [%1], %2;\n\t"\
        "selp.b32 %0, 1, 0, p;\n\t}" : "=r"(_d) : "r"(_m), "r"(_p) : "memory");\
    if (!_d) {                                                                 \
        asm volatile("{\n\t.reg .pred P1;\n\t"                                 \
            "WL_%=:\n\t"                                                       \
            "mbarrier.try_wait.parity.acquire.cta.shared::cta.b64 P1, [%0], %1, 0x989680;\n\t" \
            "@P1 bra.uni WD_%=;\n\t"                                           \
            "bra.uni WL_%=;\n\t"                                               \
            "WD_%=:\n\t}" :: "r"(_m), "r"(_p) : "memory");                     \
    }                                                                          \
} while (0)

__device__ __forceinline__ void ldsm_x4(uint32_t* r, uint32_t addr) {
    asm volatile("ldmatrix.sync.aligned.m8n8.x4.shared.b16 {%0,%1,%2,%3}, [%4];"
                 : "=r"(r[0]), "=r"(r[1]), "=r"(r[2]), "=r"(r[3]) : "r"(addr));
}

__device__ __forceinline__ void mma16816(float* c, const uint32_t* a,
                                         uint32_t b0, uint32_t b1) {
    asm volatile(
        "mma.sync.aligned.m16n8k16.row.col.f32.f16.f16.f32 "
        "{%0,%1,%2,%3}, {%4,%5,%6,%7}, {%8,%9}, {%0,%1,%2,%3};"
        : "+f"(c[0]), "+f"(c[1]), "+f"(c[2]), "+f"(c[3])
        : "r"(a[0]), "r"(a[1]), "r"(a[2]), "r"(a[3]), "r"(b0), "r"(b1));
}

// ---------------------------------------------------------------------------
// Unified prep: grid sections on blockIdx.x
//   [0, nWb)       : W [k][j] -> Wt [j][k] fp16 (32x32 transpose tiles)
//   [nWb, ...)     : fp32 -> fp16 convert of x then pos (float4 lanes)
// Block 0 / thread 0 also re-initializes the calibration atomic cells
// (every replay; ordered before calib2 on the stream).
// ---------------------------------------------------------------------------
__global__ __launch_bounds__(256)
void prep_kernel(const float* __restrict__ W, __half* __restrict__ wth, int D,
                 int nWb,
                 const float* __restrict__ x, __half* __restrict__ xh, int nx4,
                 const float* __restrict__ p, __half* __restrict__ ph, int np4)
{
    const int tid = threadIdx.x;
    const int bx  = blockIdx.x;

    if (bx < nWb) {
        if (bx == 0 && tid == 0) {
            g_cal[0] = 0;            // bits of 0.0f     (running max, n4 > 0)
            g_cal[1] = 0x7F7FFFFF;   // bits of FLT_MAX  (running min)
        }
        __shared__ float t[32][33];
        const int nJ = D / 32;
        const int j0 = (bx % nJ) * 32, k0 = (bx / nJ) * 32;
        const int tx = tid & 31, ty = tid >> 5;   // 32 x 8
        #pragma unroll
        for (int r = 0; r < 4; ++r)
            t[ty + 8 * r][tx] = W[(size_t)(k0 + ty + 8 * r) * D + j0 + tx];
        __syncthreads();
        #pragma unroll
        for (int r = 0; r < 4; ++r) {
            float v = t[tx][ty + 8 * r];
            wth[(size_t)(j0 + ty + 8 * r) * D + k0 + tx] = __float2half_rn(v);
        }
        return;
    }

    int i = (bx - nWb) * 256 + tid;
    const float* src;
    __half* dst;
    if (i < nx4) { src = x; dst = xh; }
    else         { src = p; dst = ph; i -= nx4; if (i >= np4) return; }
    float4 v = reinterpret_cast<const float4*>(src)[i];
    __half2* hp = reinterpret_cast<__half2*>(dst) + 2 * i;
    hp[0] = __half2(__float2half_rn(v.x), __float2half_rn(v.y));
    hp[1] = __half2(__float2half_rn(v.z), __float2half_rn(v.w));
}

// ---------------------------------------------------------------------------
// mma.sync GEMM-norm + fused x_dot row-norms. Grid sections on blockIdx.x:
//   [0, nxB)            : rows of X  -> xparts
//   [nxB, nxB+npB)      : rows of Pm -> pparts
//   [nxB+npB, +ndB)     : x_dot row sum-of-squares -> d2   (y==0 only)
// GEMM block: 128x128, 4 warps (2x2 of 64x64), K in 64-chunks, 3-stage
// cp.async pipeline driven by mbarriers: FULL[s] (128 cp.async arrivals),
// CONS[s] (4 per-warp elected arrivals).
// Smem tile rows: 64 halves = 128 B data, 144 B stride (conflict-free ldsm).
// ---------------------------------------------------------------------------
#define TILE_B   18432              // 128 rows * 144 B
#define A_OFF    0
#define B_OFF    (TILE_B)
#define STAGE_B  (2 * TILE_B)       // 36864
#define NSTAGE   3
#define MBAR_OFF (NSTAGE * STAGE_B)         // 110592
#define SMEM_TOTAL (MBAR_OFF + 64)          // 110656

__global__ __launch_bounds__(128, 2)
void mma_gemm_norm(const __half* __restrict__ X,
                   const __half* __restrict__ Pm,
                   const __half* __restrict__ Wm,
                   const float* __restrict__ x_dot,
                   int D, int nxB, int npB,
                   float* __restrict__ xparts, int Brows,
                   float* __restrict__ pparts, int Prows,
                   float* __restrict__ d2)
{
    extern __shared__ __align__(128) char smem[];
    const uint32_t sm0 = smem_to_u32(smem);

    const int tid  = threadIdx.x;
    const int wid  = tid >> 5;
    const int lane = tid & 31;

    // ---- section 3: x_dot row-norms (DRAM-bound filler blocks) ----------
    if ((int)blockIdx.x >= nxB + npB) {
        if (blockIdx.y != 0) return;
        const int base = ((int)blockIdx.x - nxB - npB) * 128 + wid * 32;
        const int D4 = D >> 2;
        for (int r = 0; r < 32; ++r) {
            const float4* xd = reinterpret_cast<const float4*>(x_dot)
                             + (size_t)(base + r) * D4;
            float s = 0.f;
            for (int i = lane; i < D4; i += 32) {
                float4 v = xd[i];
                s += v.x * v.x + v.y * v.y + v.z * v.z + v.w * v.w;
            }
            #pragma unroll
            for (int off = 16; off > 0; off >>= 1)
                s += __shfl_down_sync(0xFFFFFFFFu, s, off);
            if (lane == 0) d2[base + r] = s;
        }
        return;
    }

    // ---- sections 1+2: GEMM-norm ----------------------------------------
    const int wm   = wid >> 1;          // 0..1 -> rows wm*64
    const int wn   = wid & 1;           // 0..1 -> cols wn*64
    const int KC   = D / BK;            // 16

    const bool isX = ((int)blockIdx.x < nxB);
    const int  mb  = isX ? (int)blockIdx.x : (int)blockIdx.x - nxB;
    const int  m0  = mb * BM;
    const int  n0  = blockIdx.y * BN;
    float* parts   = isX ? xparts : pparts;
    const int rowStride = isX ? Brows : Prows;

    const __half* gA = (isX ? X : Pm) + (size_t)m0 * D;
    const __half* gB = Wm + (size_t)n0 * D;

    const uint32_t FULL = sm0 + MBAR_OFF;        // 3 x 8B
    const uint32_t CONS = sm0 + MBAR_OFF + 24;   // 3 x 8B

    if (tid == 0) {
        #pragma unroll
        for (int s = 0; s < NSTAGE; ++s) {
            MBARRIER_INIT(FULL + 8 * s, 128);   // all threads' cp.async groups
            MBARRIER_INIT(CONS + 8 * s, 4);     // one elected lane per warp
        }
    }
    __syncthreads();

    float acc[4][8][4];
    #pragma unroll
    for (int i = 0; i < 4; ++i)
        #pragma unroll
        for (int j = 0; j < 8; ++j)
            #pragma unroll
            for (int c = 0; c < 4; ++c) acc[i][j][c] = 0.f;

    auto load_chunk = [&](int kc, int s) {
        const uint32_t sb = sm0 + (uint32_t)s * STAGE_B;
        const int kb = kc * BK;          // halves
        #pragma unroll
        for (int i = 0; i < 8; ++i) {
            int idx = tid + 128 * i;     // 0..1023
            int r = idx >> 3, c = idx & 7;
            uint32_t so = (uint32_t)(r * 144 + c * 16);
            size_t go = (size_t)r * D + kb + c * 8;
            CP_ASYNC16(sb + A_OFF + so, gA + go);
            CP_ASYNC16(sb + B_OFF + so, gB + go);
        }
    };

    // ldmatrix per-lane address pieces (within-warp), hoisted
    const int a_row = (lane & 15);
    const int a_ku  = (lane >> 4);
    const int b_row = ((lane >> 4) << 3) + (lane & 7);
    const int b_ku  = ((lane >> 3) & 1);
    const int mrow  = wm * 64;
    const int nrow  = wn * 64;
    const uint32_t aBase0 = (uint32_t)((mrow + a_row) * 144 + a_ku * 16);
    const uint32_t bBase0 = (uint32_t)((nrow + b_row) * 144 + b_ku * 16);

    // prologue: chunks 0 and 1 in flight (deferred arrivals on FULL)
    load_chunk(0, 0);
    CP_MBAR_ARRIVE(FULL + 0);
    load_chunk(1, 1);
    CP_MBAR_ARRIVE(FULL + 8);

    for (int kc = 0; kc < KC; ++kc) {
        const int s = kc % NSTAGE;

        // produce chunk kc+2 into stage (kc+2)%3 (wait its previous reader)
        if (kc + 2 < KC) {
            const int s2 = (kc + 2) % NSTAGE;
            const uint32_t pc = (kc == 0) ? 1u : (uint32_t)(((kc - 1) / 3) & 1);
            MBARRIER_WAIT_PARITY(CONS + 8 * s2, pc);
            load_chunk(kc + 2, s2);
            CP_MBAR_ARRIVE(FULL + 8 * s2);
        }

        // consume chunk kc
        MBARRIER_WAIT_PARITY(FULL + 8 * s, (uint32_t)((kc / 3) & 1));

        const uint32_t sb = sm0 + (uint32_t)s * STAGE_B;
        const uint32_t aB = sb + A_OFF + aBase0;
        const uint32_t bB = sb + B_OFF + bBase0;
        #pragma unroll
        for (int ks = 0; ks < 4; ++ks) {        // four k16 steps per chunk
            const uint32_t kOff = (uint32_t)(ks * 32);
            uint32_t ah[4][4], bh[4][4];
            #pragma unroll
            for (int mt = 0; mt < 4; ++mt)
                ldsm_x4(ah[mt], aB + kOff + (uint32_t)(mt * 16 * 144));
            #pragma unroll
            for (int ng = 0; ng < 4; ++ng)
                ldsm_x4(bh[ng], bB + kOff + (uint32_t)(ng * 16 * 144));
            #pragma unroll
            for (int mt = 0; mt < 4; ++mt) {
                #pragma unroll
                for (int nt = 0; nt < 8; ++nt) {
                    uint32_t b0 = bh[nt >> 1][2 * (nt & 1)];
                    uint32_t b1 = bh[nt >> 1][2 * (nt & 1) + 1];
                    mma16816(acc[mt][nt], ah[mt], b0, b1);
                }
            }
        }

        // warp done reading stage s: one elected arrival per warp.
        if (lane == 0) MBARRIER_ARRIVE(CONS + 8 * s);
    }
    __syncthreads();   // all warps done (and all loads consumed) before reuse

    // ---- epilogue: row-wise sum of squares -------------------------------
    float* rbuf = reinterpret_cast<float*>(smem);   // [128][2]
    float rs0[4], rs1[4];
    #pragma unroll
    for (int mt = 0; mt < 4; ++mt) {
        float s0 = 0.f, s1 = 0.f;
        #pragma unroll
        for (int nt = 0; nt < 8; ++nt) {
            s0 += acc[mt][nt][0] * acc[mt][nt][0] + acc[mt][nt][1] * acc[mt][nt][1];
            s1 += acc[mt][nt][2] * acc[mt][nt][2] + acc[mt][nt][3] * acc[mt][nt][3];
        }
        s0 += __shfl_xor_sync(0xFFFFFFFFu, s0, 1);
        s0 += __shfl_xor_sync(0xFFFFFFFFu, s0, 2);
        s1 += __shfl_xor_sync(0xFFFFFFFFu, s1, 1);
        s1 += __shfl_xor_sync(0xFFFFFFFFu, s1, 2);
        rs0[mt] = s0;
        rs1[mt] = s1;
    }
    if ((lane & 3) == 0) {
        int rq = lane >> 2;
        #pragma unroll
        for (int mt = 0; mt < 4; ++mt) {
            int row = mrow + mt * 16 + rq;
            rbuf[row * 2 + wn] = rs0[mt];
            rbuf[(row + 8) * 2 + wn] = rs1[mt];
        }
    }
    __syncthreads();
    if (tid < BM) {
        float tot = rbuf[tid * 2 + 0] + rbuf[tid * 2 + 1];
        parts[(size_t)blockIdx.y * rowStride + m0 + tid] = tot;
    }
}

// ---------------------------------------------------------------------------
// Calibration: per-row n2 -> n4; block-reduce max/min; ONE atomicMax/Min per
// block on int-punned positive floats (bit order == float order for +vals;
// max/min commutative -> deterministic, same alpha/beta bits as serial).
// ---------------------------------------------------------------------------
__global__ __launch_bounds__(256)
void calib2_kernel(const float* __restrict__ pparts, int P, int nparts,
                   int* __restrict__ cal)
{
    __shared__ float smx[256], smn[256];
    const int tid = threadIdx.x;
    const int r = blockIdx.x * 256 + tid;

    float n4;
    {
        float n2 = 0.f;
        for (int y = 0; y < nparts; ++y) n2 += pparts[(size_t)y * P + r];
        n4 = n2 * n2;
    }
    smx[tid] = n4;
    smn[tid] = n4;
    __syncthreads();
    for (int s = 128; s > 0; s >>= 1) {
        if (tid < s) {
            smx[tid] = fmaxf(smx[tid], smx[tid + s]);
            smn[tid] = fminf(smn[tid], smn[tid + s]);
        }
        __syncthreads();
    }
    if (tid == 0) {
        atomicMax(&cal[0], __float_as_int(smx[0]));
        atomicMin(&cal[1], __float_as_int(smn[0]));
    }
}

// ---------------------------------------------------------------------------
// Combine: out[b] = (alpha*n2^2 + beta) * d2[b];  alpha/beta from 2 scalars.
// ---------------------------------------------------------------------------
__global__ __launch_bounds__(256)
void combine_kernel(const float* __restrict__ xparts, int nparts,
                    const int* __restrict__ cal,
                    const float* __restrict__ d2,
                    float* __restrict__ out, int B)
{
    const int b = blockIdx.x * blockDim.x + threadIdx.x;
    if (b >= B) return;
    const float mx = __int_as_float(cal[0]);
    const float mn = __int_as_float(cal[1]);
    const float alpha = (1.0f - 0.001f) / (mx - mn);
    const float beta  = 0.001f - alpha * mn;
    float n2 = 0.f;
    for (int y = 0; y < nparts; ++y) n2 += xparts[(size_t)y * B + b];
    out[b] = (alpha * n2 * n2 + beta) * d2[b];
}

// ---------------------------------------------------------------------------
// kernel_launch
// ---------------------------------------------------------------------------
extern "C" void kernel_launch(void* const* d_in, const int* in_sizes, int n_in,
                              void* d_out, int out_size)
{
    const float* x     = (const float*)d_in[0];
    const float* x_dot = (const float*)d_in[1];
    const float* pos   = (const float*)d_in[2];
    const float* W     = (const float*)d_in[3];
    float* out = (float*)d_out;

    const int D = (int)(sqrt((double)in_sizes[3]) + 0.5);
    const int B = in_sizes[0] / D;
    const int P = in_sizes[2] / D;
    const int NS = D / BN;   // 8 N-slices

    __half *xh, *ph, *wh;
    float *xparts, *pparts, *d2;
    int *cal;
    cudaGetSymbolAddress((void**)&xh, g_xh);
    cudaGetSymbolAddress((void**)&ph, g_ph);
    cudaGetSymbolAddress((void**)&wh, g_wh);
    cudaGetSymbolAddress((void**)&xparts, g_xparts);
    cudaGetSymbolAddress((void**)&pparts, g_pparts);
    cudaGetSymbolAddress((void**)&d2, g_d2);
    cudaGetSymbolAddress((void**)&cal, g_cal);

    cudaFuncSetAttribute(mma_gemm_norm,
                         cudaFuncAttributeMaxDynamicSharedMemorySize, SMEM_TOTAL);

    // unified prep: W transpose + fp16 converts + calib-cell init
    const int nWb = (D / 32) * (D / 32);
    const int nx4 = (B * D) / 4;
    const int np4 = (P * D) / 4;
    const int nCvtB = (nx4 + np4 + 255) / 256;
    prep_kernel<<<nWb + nCvtB, 256>>>(W, wh, D, nWb, x, xh, nx4, pos, ph, np4);

    // merged x-gemm + pos-gemm + x_dot row-norms (single launch)
    const int nxB = B / BM;
    const int npB = P / BM;
    const int ndB = B / 128;
    mma_gemm_norm<<<dim3(nxB + npB + ndB, NS), 128, SMEM_TOTAL>>>(
        xh, ph, wh, x_dot, D, nxB, npB, xparts, B, pparts, P, d2);

    // calibration (atomic max/min, deterministic)
    calib2_kernel<<<P / 256, 256>>>(pparts, P, NS, cal);

    // combine
    combine_kernel<<<(B + 255) / 256, 256>>>(xparts, NS, cal, d2, out, B);
}

// round 12
// speedup vs baseline: 11.8106x; 1.0270x over previous
#include <cuda_runtime.h>
#include <cuda_fp16.h>
#include <math.h>
#include <stdint.h>

// ===========================================================================
// ScoreMagnitudeMetric via warp-level mma.sync fp16 single-term GEMM:
//   scores = x @ W  ~=  fp16(x) @ fp16(W^T)   (fp32 accumulation)
//   n2[b] = ||scores_b||^2 ; out[b] = (alpha*n2^2 + beta) * ||x_dot_b||^2
// R12: BM=256 mega-CTA (256 threads, 8 warps 4x2, 1 CTA/SM) -> B-tile LDSM
// fragments amortized over 2x the MMAs; ~8% less crossbar per HMMA and half
// the mbarrier ops per SM. Everything else as R11.
// ===========================================================================

#define MAXB 32768
#define MAXP 2048
#define MAXD 1024

#define BM 256
#define BN 128
#define BK 64
#define NSLICE_MAX (MAXD / BN)   // 8

// scratch (device globals; no allocation allowed)
__device__ __half g_xh[(size_t)MAXB * MAXD];
__device__ __half g_ph[(size_t)MAXP * MAXD];
__device__ __half g_wh[(size_t)MAXD * MAXD];   // fp16(W^T)
__device__ float g_xparts[NSLICE_MAX * MAXB];
__device__ float g_pparts[NSLICE_MAX * MAXP];
__device__ float g_d2[MAXB];
__device__ int   g_cal[2];                     // [0]=max(n4) bits, [1]=min(n4) bits

// ---------------------------------------------------------------------------
// helpers
// ---------------------------------------------------------------------------
__device__ __forceinline__ uint32_t smem_to_u32(const void* p) {
    uint32_t a;
    asm("{ .reg .u64 t; cvta.to.shared.u64 t, %1; cvt.u32.u64 %0, t; }"
        : "=r"(a) : "l"(p));
    return a;
}

#define CP_ASYNC16(sm, g) \
    asm volatile("cp.async.cg.shared.global [%0], [%1], 16;" :: "r"(sm), "l"(g) : "memory")

// deferred arrival on mbar when all prior cp.async of this thread complete
#define CP_MBAR_ARRIVE(mbar) \
    asm volatile("cp.async.mbarrier.arrive.noinc.shared.b64 [%0];" \
                 :: "r"((uint32_t)(mbar)) : "memory")

#define MBARRIER_INIT(addr, cnt) \
    asm volatile("mbarrier.init.shared.b64 [%0], %1;" \
                 :: "r"((uint32_t)(addr)), "r"((uint32_t)(cnt)) : "memory")

#define MBARRIER_ARRIVE(addr) \
    asm volatile("mbarrier.arrive.shared.b64 _, [%0];" \
                 :: "r"((uint32_t)(addr)) : "memory")

#define MBARRIER_WAIT_PARITY(addr, par) do {                                   \
    uint32_t _m = (uint32_t)(addr); uint32_t _p = (uint32_t)(par); uint32_t _d;\
    asm volatile("{\n\t.reg .pred p;\n\t"                                      \
        "mbarrier.try_wait.parity.acquire.cta.shared::cta.b64 p, [%1], %2;\n\t"\
        "selp.b32 %0, 1, 0, p;\n\t}" : "=r"(_d) : "r"(_m), "r"(_p) : "memory");\
    if (!_d) {                                                                 \
        asm volatile("{\n\t.reg .pred P1;\n\t"                                 \
            "WL_%=:\n\t"                                                       \
            "mbarrier.try_wait.parity.acquire.cta.shared::cta.b64 P1, [%0], %1, 0x989680;\n\t" \
            "@P1 bra.uni WD_%=;\n\t"                                           \
            "bra.uni WL_%=;\n\t"                                               \
            "WD_%=:\n\t}" :: "r"(_m), "r"(_p) : "memory");                     \
    }                                                                          \
} while (0)

__device__ __forceinline__ void ldsm_x4(uint32_t* r, uint32_t addr) {
    asm volatile("ldmatrix.sync.aligned.m8n8.x4.shared.b16 {%0,%1,%2,%3}, [%4];"
                 : "=r"(r[0]), "=r"(r[1]), "=r"(r[2]), "=r"(r[3]) : "r"(addr));
}

__device__ __forceinline__ void mma16816(float* c, const uint32_t* a,
                                         uint32_t b0, uint32_t b1) {
    asm volatile(
        "mma.sync.aligned.m16n8k16.row.col.f32.f16.f16.f32 "
        "{%0,%1,%2,%3}, {%4,%5,%6,%7}, {%8,%9}, {%0,%1,%2,%3};"
        : "+f"(c[0]), "+f"(c[1]), "+f"(c[2]), "+f"(c[3])
        : "r"(a[0]), "r"(a[1]), "r"(a[2]), "r"(a[3]), "r"(b0), "r"(b1));
}

// ---------------------------------------------------------------------------
// Unified prep: grid sections on blockIdx.x
//   [0, nWb)       : W [k][j] -> Wt [j][k] fp16 (32x32 transpose tiles)
//   [nWb, ...)     : fp32 -> fp16 convert of x then pos (float4 lanes)
// Block 0 / thread 0 also re-initializes the calibration atomic cells.
// ---------------------------------------------------------------------------
__global__ __launch_bounds__(256)
void prep_kernel(const float* __restrict__ W, __half* __restrict__ wth, int D,
                 int nWb,
                 const float* __restrict__ x, __half* __restrict__ xh, int nx4,
                 const float* __restrict__ p, __half* __restrict__ ph, int np4)
{
    const int tid = threadIdx.x;
    const int bx  = blockIdx.x;

    if (bx < nWb) {
        if (bx == 0 && tid == 0) {
            g_cal[0] = 0;            // bits of 0.0f     (running max, n4 > 0)
            g_cal[1] = 0x7F7FFFFF;   // bits of FLT_MAX  (running min)
        }
        __shared__ float t[32][33];
        const int nJ = D / 32;
        const int j0 = (bx % nJ) * 32, k0 = (bx / nJ) * 32;
        const int tx = tid & 31, ty = tid >> 5;   // 32 x 8
        #pragma unroll
        for (int r = 0; r < 4; ++r)
            t[ty + 8 * r][tx] = W[(size_t)(k0 + ty + 8 * r) * D + j0 + tx];
        __syncthreads();
        #pragma unroll
        for (int r = 0; r < 4; ++r) {
            float v = t[tx][ty + 8 * r];
            wth[(size_t)(j0 + ty + 8 * r) * D + k0 + tx] = __float2half_rn(v);
        }
        return;
    }

    int i = (bx - nWb) * 256 + tid;
    const float* src;
    __half* dst;
    if (i < nx4) { src = x; dst = xh; }
    else         { src = p; dst = ph; i -= nx4; if (i >= np4) return; }
    float4 v = reinterpret_cast<const float4*>(src)[i];
    __half2* hp = reinterpret_cast<__half2*>(dst) + 2 * i;
    hp[0] = __half2(__float2half_rn(v.x), __float2half_rn(v.y));
    hp[1] = __half2(__float2half_rn(v.z), __float2half_rn(v.w));
}

// ---------------------------------------------------------------------------
// mma.sync GEMM-norm + fused x_dot row-norms. Grid sections on blockIdx.x:
//   [0, nxB)            : 256-row tiles of X  -> xparts
//   [nxB, nxB+npB)      : 256-row tiles of Pm -> pparts
//   [nxB+npB, +ndB)     : x_dot row sum-of-squares (256 rows/blk) -> d2 (y==0)
// GEMM block: 256 rows x 128 cols, 8 warps (4x2 of 64x64), 256 threads,
// 1 CTA/SM.  K in 64-chunks, 3-stage cp.async pipeline via mbarriers:
// FULL[s] (256 cp.async arrivals), CONS[s] (8 per-warp elected arrivals).
// Smem tile rows: 64 halves = 128 B data, 144 B stride (conflict-free ldsm).
// ---------------------------------------------------------------------------
#define A_TILE_B (256 * 144)                // 36864
#define B_TILE_B (128 * 144)                // 18432
#define A_OFF    0
#define B_OFF    (A_TILE_B)
#define STAGE_B  (A_TILE_B + B_TILE_B)      // 55296
#define NSTAGE   3
#define MBAR_OFF (NSTAGE * STAGE_B)         // 165888
#define SMEM_TOTAL (MBAR_OFF + 64)          // 165952

__global__ __launch_bounds__(256, 1)
void mma_gemm_norm(const __half* __restrict__ X,
                   const __half* __restrict__ Pm,
                   const __half* __restrict__ Wm,
                   const float* __restrict__ x_dot,
                   int D, int nxB, int npB,
                   float* __restrict__ xparts, int Brows,
                   float* __restrict__ pparts, int Prows,
                   float* __restrict__ d2)
{
    extern __shared__ __align__(128) char smem[];
    const uint32_t sm0 = smem_to_u32(smem);

    const int tid  = threadIdx.x;
    const int wid  = tid >> 5;
    const int lane = tid & 31;

    // ---- section 3: x_dot row-norms (DRAM-bound filler blocks) ----------
    if ((int)blockIdx.x >= nxB + npB) {
        if (blockIdx.y != 0) return;
        const int base = ((int)blockIdx.x - nxB - npB) * 256 + wid * 32;
        const int D4 = D >> 2;
        for (int r = 0; r < 32; ++r) {
            const float4* xd = reinterpret_cast<const float4*>(x_dot)
                             + (size_t)(base + r) * D4;
            float s = 0.f;
            for (int i = lane; i < D4; i += 32) {
                float4 v = xd[i];
                s += v.x * v.x + v.y * v.y + v.z * v.z + v.w * v.w;
            }
            #pragma unroll
            for (int off = 16; off > 0; off >>= 1)
                s += __shfl_down_sync(0xFFFFFFFFu, s, off);
            if (lane == 0) d2[base + r] = s;
        }
        return;
    }

    // ---- sections 1+2: GEMM-norm ----------------------------------------
    const int wm   = wid >> 1;          // 0..3 -> rows wm*64
    const int wn   = wid & 1;           // 0..1 -> cols wn*64
    const int KC   = D / BK;            // 16

    const bool isX = ((int)blockIdx.x < nxB);
    const int  mb  = isX ? (int)blockIdx.x : (int)blockIdx.x - nxB;
    const int  m0  = mb * BM;
    const int  n0  = blockIdx.y * BN;
    float* parts   = isX ? xparts : pparts;
    const int rowStride = isX ? Brows : Prows;

    const __half* gA = (isX ? X : Pm) + (size_t)m0 * D;
    const __half* gB = Wm + (size_t)n0 * D;

    const uint32_t FULL = sm0 + MBAR_OFF;        // 3 x 8B
    const uint32_t CONS = sm0 + MBAR_OFF + 24;   // 3 x 8B

    if (tid == 0) {
        #pragma unroll
        for (int s = 0; s < NSTAGE; ++s) {
            MBARRIER_INIT(FULL + 8 * s, 256);   // all threads' cp.async groups
            MBARRIER_INIT(CONS + 8 * s, 8);     // one elected lane per warp
        }
    }
    __syncthreads();

    float acc[4][8][4];
    #pragma unroll
    for (int i = 0; i < 4; ++i)
        #pragma unroll
        for (int j = 0; j < 8; ++j)
            #pragma unroll
            for (int c = 0; c < 4; ++c) acc[i][j][c] = 0.f;

    auto load_chunk = [&](int kc, int s) {
        const uint32_t sb = sm0 + (uint32_t)s * STAGE_B;
        const int kb = kc * BK;          // halves
        // A: 256 rows x 8 16B-segments = 2048 units; 8 per thread
        #pragma unroll
        for (int i = 0; i < 8; ++i) {
            int idx = tid + 256 * i;     // 0..2047
            int r = idx >> 3, c = idx & 7;
            uint32_t so = (uint32_t)(r * 144 + c * 16);
            CP_ASYNC16(sb + A_OFF + so, gA + (size_t)r * D + kb + c * 8);
        }
        // B: 128 rows x 8 segments = 1024 units; 4 per thread
        #pragma unroll
        for (int i = 0; i < 4; ++i) {
            int idx = tid + 256 * i;     // 0..1023
            int r = idx >> 3, c = idx & 7;
            uint32_t so = (uint32_t)(r * 144 + c * 16);
            CP_ASYNC16(sb + B_OFF + so, gB + (size_t)r * D + kb + c * 8);
        }
    };

    // ldmatrix per-lane address pieces (within-warp), hoisted
    const int a_row = (lane & 15);
    const int a_ku  = (lane >> 4);
    const int b_row = ((lane >> 4) << 3) + (lane & 7);
    const int b_ku  = ((lane >> 3) & 1);
    const int mrow  = wm * 64;
    const int nrow  = wn * 64;
    const uint32_t aBase0 = (uint32_t)((mrow + a_row) * 144 + a_ku * 16);
    const uint32_t bBase0 = (uint32_t)((nrow + b_row) * 144 + b_ku * 16);

    // prologue: chunks 0 and 1 in flight (deferred arrivals on FULL)
    load_chunk(0, 0);
    CP_MBAR_ARRIVE(FULL + 0);
    load_chunk(1, 1);
    CP_MBAR_ARRIVE(FULL + 8);

    for (int kc = 0; kc < KC; ++kc) {
        const int s = kc % NSTAGE;

        // produce chunk kc+2 into stage (kc+2)%3 (wait its previous reader)
        if (kc + 2 < KC) {
            const int s2 = (kc + 2) % NSTAGE;
            const uint32_t pc = (kc == 0) ? 1u : (uint32_t)(((kc - 1) / 3) & 1);
            MBARRIER_WAIT_PARITY(CONS + 8 * s2, pc);
            load_chunk(kc + 2, s2);
            CP_MBAR_ARRIVE(FULL + 8 * s2);
        }

        // consume chunk kc
        MBARRIER_WAIT_PARITY(FULL + 8 * s, (uint32_t)((kc / 3) & 1));

        const uint32_t sb = sm0 + (uint32_t)s * STAGE_B;
        const uint32_t aB = sb + A_OFF + aBase0;
        const uint32_t bB = sb + B_OFF + bBase0;
        #pragma unroll
        for (int ks = 0; ks < 4; ++ks) {        // four k16 steps per chunk
            const uint32_t kOff = (uint32_t)(ks * 32);
            uint32_t ah[4][4], bh[4][4];
            #pragma unroll
            for (int mt = 0; mt < 4; ++mt)
                ldsm_x4(ah[mt], aB + kOff + (uint32_t)(mt * 16 * 144));
            #pragma unroll
            for (int ng = 0; ng < 4; ++ng)
                ldsm_x4(bh[ng], bB + kOff + (uint32_t)(ng * 16 * 144));
            #pragma unroll
            for (int mt = 0; mt < 4; ++mt) {
                #pragma unroll
                for (int nt = 0; nt < 8; ++nt) {
                    uint32_t b0 = bh[nt >> 1][2 * (nt & 1)];
                    uint32_t b1 = bh[nt >> 1][2 * (nt & 1) + 1];
                    mma16816(acc[mt][nt], ah[mt], b0, b1);
                }
            }
        }

        // warp done reading stage s: one elected arrival per warp.
        if (lane == 0) MBARRIER_ARRIVE(CONS + 8 * s);
    }
    __syncthreads();   // all warps done (and all loads consumed) before reuse

    // ---- epilogue: row-wise sum of squares -------------------------------
    float* rbuf = reinterpret_cast<float*>(smem);   // [256][2]
    float rs0[4], rs1[4];
    #pragma unroll
    for (int mt = 0; mt < 4; ++mt) {
        float s0 = 0.f, s1 = 0.f;
        #pragma unroll
        for (int nt = 0; nt < 8; ++nt) {
            s0 += acc[mt][nt][0] * acc[mt][nt][0] + acc[mt][nt][1] * acc[mt][nt][1];
            s1 += acc[mt][nt][2] * acc[mt][nt][2] + acc[mt][nt][3] * acc[mt][nt][3];
        }
        s0 += __shfl_xor_sync(0xFFFFFFFFu, s0, 1);
        s0 += __shfl_xor_sync(0xFFFFFFFFu, s0, 2);
        s1 += __shfl_xor_sync(0xFFFFFFFFu, s1, 1);
        s1 += __shfl_xor_sync(0xFFFFFFFFu, s1, 2);
        rs0[mt] = s0;
        rs1[mt] = s1;
    }
    if ((lane & 3) == 0) {
        int rq = lane >> 2;
        #pragma unroll
        for (int mt = 0; mt < 4; ++mt) {
            int row = mrow + mt * 16 + rq;
            rbuf[row * 2 + wn] = rs0[mt];
            rbuf[(row + 8) * 2 + wn] = rs1[mt];
        }
    }
    __syncthreads();
    if (tid < BM) {
        float tot = rbuf[tid * 2 + 0] + rbuf[tid * 2 + 1];
        parts[(size_t)blockIdx.y * rowStride + m0 + tid] = tot;
    }
}

// ---------------------------------------------------------------------------
// Calibration: per-row n2 -> n4; block-reduce max/min; ONE atomicMax/Min per
// block on int-punned positive floats (deterministic).
// ---------------------------------------------------------------------------
__global__ __launch_bounds__(256)
void calib2_kernel(const float* __restrict__ pparts, int P, int nparts,
                   int* __restrict__ cal)
{
    __shared__ float smx[256], smn[256];
    const int tid = threadIdx.x;
    const int r = blockIdx.x * 256 + tid;

    float n4;
    {
        float n2 = 0.f;
        for (int y = 0; y < nparts; ++y) n2 += pparts[(size_t)y * P + r];
        n4 = n2 * n2;
    }
    smx[tid] = n4;
    smn[tid] = n4;
    __syncthreads();
    for (int s = 128; s > 0; s >>= 1) {
        if (tid < s) {
            smx[tid] = fmaxf(smx[tid], smx[tid + s]);
            smn[tid] = fminf(smn[tid], smn[tid + s]);
        }
        __syncthreads();
    }
    if (tid == 0) {
        atomicMax(&cal[0], __float_as_int(smx[0]));
        atomicMin(&cal[1], __float_as_int(smn[0]));
    }
}

// ---------------------------------------------------------------------------
// Combine: out[b] = (alpha*n2^2 + beta) * d2[b];  alpha/beta from 2 scalars.
// ---------------------------------------------------------------------------
__global__ __launch_bounds__(256)
void combine_kernel(const float* __restrict__ xparts, int nparts,
                    const int* __restrict__ cal,
                    const float* __restrict__ d2,
                    float* __restrict__ out, int B)
{
    const int b = blockIdx.x * blockDim.x + threadIdx.x;
    if (b >= B) return;
    const float mx = __int_as_float(cal[0]);
    const float mn = __int_as_float(cal[1]);
    const float alpha = (1.0f - 0.001f) / (mx - mn);
    const float beta  = 0.001f - alpha * mn;
    float n2 = 0.f;
    for (int y = 0; y < nparts; ++y) n2 += xparts[(size_t)y * B + b];
    out[b] = (alpha * n2 * n2 + beta) * d2[b];
}

// ---------------------------------------------------------------------------
// kernel_launch
// ---------------------------------------------------------------------------
extern "C" void kernel_launch(void* const* d_in, const int* in_sizes, int n_in,
                              void* d_out, int out_size)
{
    const float* x     = (const float*)d_in[0];
    const float* x_dot = (const float*)d_in[1];
    const float* pos   = (const float*)d_in[2];
    const float* W     = (const float*)d_in[3];
    float* out = (float*)d_out;

    const int D = (int)(sqrt((double)in_sizes[3]) + 0.5);
    const int B = in_sizes[0] / D;
    const int P = in_sizes[2] / D;
    const int NS = D / BN;   // 8 N-slices

    __half *xh, *ph, *wh;
    float *xparts, *pparts, *d2;
    int *cal;
    cudaGetSymbolAddress((void**)&xh, g_xh);
    cudaGetSymbolAddress((void**)&ph, g_ph);
    cudaGetSymbolAddress((void**)&wh, g_wh);
    cudaGetSymbolAddress((void**)&xparts, g_xparts);
    cudaGetSymbolAddress((void**)&pparts, g_pparts);
    cudaGetSymbolAddress((void**)&d2, g_d2);
    cudaGetSymbolAddress((void**)&cal, g_cal);

    cudaFuncSetAttribute(mma_gemm_norm,
                         cudaFuncAttributeMaxDynamicSharedMemorySize, SMEM_TOTAL);

    // unified prep: W transpose + fp16 converts + calib-cell init
    const int nWb = (D / 32) * (D / 32);
    const int nx4 = (B * D) / 4;
    const int np4 = (P * D) / 4;
    const int nCvtB = (nx4 + np4 + 255) / 256;
    prep_kernel<<<nWb + nCvtB, 256>>>(W, wh, D, nWb, x, xh, nx4, pos, ph, np4);

    // merged x-gemm + pos-gemm + x_dot row-norms (single launch)
    const int nxB = B / BM;          // 128
    const int npB = P / BM;          // 8
    const int ndB = B / 256;         // 128 (x_dot filler, 256 rows/block)
    mma_gemm_norm<<<dim3(nxB + npB + ndB, NS), 256, SMEM_TOTAL>>>(
        xh, ph, wh, x_dot, D, nxB, npB, xparts, B, pparts, P, d2);

    // calibration (atomic max/min, deterministic)
    calib2_kernel<<<P / 256, 256>>>(pparts, P, NS, cal);

    // combine
    combine_kernel<<<(B + 255) / 256, 256>>>(xparts, NS, cal, d2, out, B);
}